// round 2
// baseline (speedup 1.0000x reference)
#include <cuda_runtime.h>

#define LRELU_SLOPE 0.3f
#define BN_EPS 1e-5f

// Scratch: [t][b][c][h][w] : 4 x 16 x 64 x 16 x 512 floats = 134 MB
__device__ float g_qkvp[4u * 16u * 64u * 16u * 512u];

struct ConvParams {
    const float* x;
    const float* w[4];
    const float* gamma[4];
    const float* beta[4];
    const float* mean[4];
    const float* var[4];
};

// ---------------------------------------------------------------------------
// Conv(1,5) + folded BN + LeakyReLU for all 4 branches.
// grid (8, 16, 16) = (tc-group of 32, h, b); 256 threads.
// Thread tile: 4 consecutive w  x  16 (t,c) outputs.
// ---------------------------------------------------------------------------
__global__ void conv_kernel(ConvParams P) {
    extern __shared__ float sm[];
    float* xs     = sm;                    // 32 * 520 floats (x row, +2 halo at idx 0..1)
    float* wf4    = xs + 32 * 520;         // 32 tc * 32 ci * 4 floats (taps 0..3, scaled)
    float* wf1    = wf4 + 32 * 32 * 4;     // 32 tc * 32 ci         (tap 4, scaled)
    float* sscale = wf1 + 32 * 32;         // 32
    float* sshift = sscale + 32;           // 32

    const int s   = blockIdx.x;   // tc group
    const int h   = blockIdx.y;
    const int b   = blockIdx.z;
    const int tid = threadIdx.x;
    const int tcbase = s * 32;

    // BN scale/shift per (t,c)
    if (tid < 32) {
        int tc = tcbase + tid;
        int t = tc >> 6, c = tc & 63;
        float sc = P.gamma[t][c] * rsqrtf(P.var[t][c] + BN_EPS);
        sscale[tid] = sc;
        sshift[tid] = P.beta[t][c] - P.mean[t][c] * sc;
    }
    __syncthreads();

    // Fold scale into weights
    for (int k = 0; k < 4; k++) {
        int p   = tid + k * 256;          // 0..1023 over 32 tc * 32 ci
        int tcl = p >> 5, ci = p & 31;
        int tc  = tcbase + tcl;
        int t = tc >> 6, c = tc & 63;
        const float* src = P.w[t] + (c * 32 + ci) * 5;
        float sc = sscale[tcl];
        ((float4*)wf4)[tcl * 32 + ci] =
            make_float4(src[0] * sc, src[1] * sc, src[2] * sc, src[3] * sc);
        wf1[tcl * 32 + ci] = src[4] * sc;
    }

    // Stage x row: xs[ci*520 + 2 + w]; halos zero.
    for (int it = 0; it < 16; it++) {
        int li = it * 1024 + tid * 4;     // over 32*512
        int ci = li >> 9, w = li & 511;
        float4 v = *(const float4*)(P.x + ((b * 32 + ci) * 16 + h) * 512 + w);
        float* d = xs + ci * 520 + 2 + w;
        d[0] = v.x; d[1] = v.y; d[2] = v.z; d[3] = v.w;
    }
    if (tid < 64) {
        int ci = tid >> 1, pp = tid & 1;
        xs[ci * 520 + pp]       = 0.0f;
        xs[ci * 520 + 514 + pp] = 0.0f;
    }
    __syncthreads();

    const int lane = tid & 31, ww = tid >> 5;
    const int wseg = ww & 3;
    const int tcs  = (ww >> 2) * 16;      // 0 or 16 (local tc base)
    const int wb   = wseg * 128 + lane * 4;

    float acc[16][4];
#pragma unroll
    for (int j = 0; j < 16; j++)
#pragma unroll
        for (int u = 0; u < 4; u++) acc[j][u] = 0.0f;

#pragma unroll 2
    for (int ci = 0; ci < 32; ci++) {
        const float* xr = xs + ci * 520 + wb;   // xr[0] == x[wb-2]
        float4 xa = *(const float4*)xr;
        float4 xb = *(const float4*)(xr + 4);
        float x0 = xa.x, x1 = xa.y, x2 = xa.z, x3 = xa.w;
        float x4 = xb.x, x5 = xb.y, x6 = xb.z, x7 = xb.w;
#pragma unroll
        for (int j = 0; j < 16; j++) {
            float4 w4 = ((const float4*)wf4)[(tcs + j) * 32 + ci];
            float  we = wf1[(tcs + j) * 32 + ci];
            acc[j][0] += w4.x * x0 + w4.y * x1 + w4.z * x2 + w4.w * x3 + we * x4;
            acc[j][1] += w4.x * x1 + w4.y * x2 + w4.z * x3 + w4.w * x4 + we * x5;
            acc[j][2] += w4.x * x2 + w4.y * x3 + w4.z * x4 + w4.w * x5 + we * x6;
            acc[j][3] += w4.x * x3 + w4.y * x4 + w4.z * x5 + w4.w * x6 + we * x7;
        }
    }

#pragma unroll
    for (int j = 0; j < 16; j++) {
        int tc = tcbase + tcs + j;
        int t = tc >> 6, c = tc & 63;
        float sh = sshift[tcs + j];
        float4 o;
        float v;
        v = acc[j][0] + sh; o.x = (v >= 0.0f) ? v : LRELU_SLOPE * v;
        v = acc[j][1] + sh; o.y = (v >= 0.0f) ? v : LRELU_SLOPE * v;
        v = acc[j][2] + sh; o.z = (v >= 0.0f) ? v : LRELU_SLOPE * v;
        v = acc[j][3] + sh; o.w = (v >= 0.0f) ? v : LRELU_SLOPE * v;
        float* dst = g_qkvp + (size_t)(((t * 16 + b) * 64 + c) * 16 + h) * 512 + wb;
        *(float4*)dst = o;
    }
}

// ---------------------------------------------------------------------------
// Attention per (b,c):  A = Q^T K (512x512, K=16), softmax rows,
// O = V @ A (16x512, K=512) + PE.
// 1024 CTAs, 256 threads, 160 KB dynamic SMEM.
// ---------------------------------------------------------------------------
__global__ void attn_kernel(float* __restrict__ out) {
    extern __shared__ float sm[];
    float* Qs = sm;              // 16*512
    float* Ks = Qs + 8192;       // 16*512
    float* Vs = Ks + 8192;       // 16*512
    float* Ss = Vs + 8192;       // 32*512 (current softmaxed row block)

    const int bc   = blockIdx.x;           // b*64 + c
    const int tid  = threadIdx.x;
    const int lane = tid & 31, ww = tid >> 5;

    // Stage Q, K, V
    {
        const float4* q = (const float4*)(g_qkvp + (size_t)(0 * 1024 + bc) * 8192);
        const float4* k = (const float4*)(g_qkvp + (size_t)(1 * 1024 + bc) * 8192);
        const float4* v = (const float4*)(g_qkvp + (size_t)(2 * 1024 + bc) * 8192);
        for (int i = tid; i < 2048; i += 256) {
            ((float4*)Qs)[i] = q[i];
            ((float4*)Ks)[i] = k[i];
            ((float4*)Vs)[i] = v[i];
        }
    }
    __syncthreads();

    float o[16][2];
#pragma unroll
    for (int hh = 0; hh < 16; hh++) { o[hh][0] = 0.0f; o[hh][1] = 0.0f; }

    const int c0 = ww * 64 + lane * 2;     // this thread's output columns

    for (int blk = 0; blk < 16; blk++) {
        // ---- Phase A: warp ww computes softmax rows r0..r0+3 ----
        float a[4][16];
#pragma unroll
        for (int r = 0; r < 4; r++)
#pragma unroll
            for (int j = 0; j < 16; j++) a[r][j] = 0.0f;

        const int r0 = blk * 32 + ww * 4;
#pragma unroll 1
        for (int h = 0; h < 16; h++) {
            const float* qrow = Qs + h * 512 + r0;
            float q0 = qrow[0], q1 = qrow[1], q2 = qrow[2], q3 = qrow[3];
            const float* krow = Ks + h * 512 + lane * 4;
#pragma unroll
            for (int j4 = 0; j4 < 4; j4++) {
                float4 kv = *(const float4*)(krow + j4 * 128);
                a[0][j4 * 4 + 0] += q0 * kv.x; a[0][j4 * 4 + 1] += q0 * kv.y;
                a[0][j4 * 4 + 2] += q0 * kv.z; a[0][j4 * 4 + 3] += q0 * kv.w;
                a[1][j4 * 4 + 0] += q1 * kv.x; a[1][j4 * 4 + 1] += q1 * kv.y;
                a[1][j4 * 4 + 2] += q1 * kv.z; a[1][j4 * 4 + 3] += q1 * kv.w;
                a[2][j4 * 4 + 0] += q2 * kv.x; a[2][j4 * 4 + 1] += q2 * kv.y;
                a[2][j4 * 4 + 2] += q2 * kv.z; a[2][j4 * 4 + 3] += q2 * kv.w;
                a[3][j4 * 4 + 0] += q3 * kv.x; a[3][j4 * 4 + 1] += q3 * kv.y;
                a[3][j4 * 4 + 2] += q3 * kv.z; a[3][j4 * 4 + 3] += q3 * kv.w;
            }
        }

#pragma unroll
        for (int r = 0; r < 4; r++) {
            float m = a[r][0];
#pragma unroll
            for (int j = 1; j < 16; j++) m = fmaxf(m, a[r][j]);
#pragma unroll
            for (int off = 16; off > 0; off >>= 1)
                m = fmaxf(m, __shfl_xor_sync(0xffffffffu, m, off));
            float ssum = 0.0f;
#pragma unroll
            for (int j = 0; j < 16; j++) {
                float e = __expf(a[r][j] - m);
                a[r][j] = e;
                ssum += e;
            }
#pragma unroll
            for (int off = 16; off > 0; off >>= 1)
                ssum += __shfl_xor_sync(0xffffffffu, ssum, off);
            float inv = 1.0f / ssum;
            float* srow = Ss + (ww * 4 + r) * 512 + lane * 4;
#pragma unroll
            for (int j4 = 0; j4 < 4; j4++) {
                *(float4*)(srow + j4 * 128) =
                    make_float4(a[r][j4 * 4 + 0] * inv, a[r][j4 * 4 + 1] * inv,
                                a[r][j4 * 4 + 2] * inv, a[r][j4 * 4 + 3] * inv);
            }
        }
        __syncthreads();

        // ---- Phase B: accumulate O[:, c0..c0+1] over this w block ----
#pragma unroll 2
        for (int w = 0; w < 32; w++) {
            int wg = blk * 32 + w;
            float2 p = *(const float2*)(Ss + w * 512 + c0);
            const float* vcol = Vs + wg;
#pragma unroll
            for (int hh = 0; hh < 16; hh++) {
                float vv = vcol[hh * 512];
                o[hh][0] += vv * p.x;
                o[hh][1] += vv * p.y;
            }
        }
        __syncthreads();   // protect Ss before next block overwrites it
    }

    // Epilogue: add PE, store
    const float* pe = g_qkvp + (size_t)(3 * 1024 + bc) * 8192;
    float* dst = out + (size_t)bc * 8192;
#pragma unroll
    for (int hh = 0; hh < 16; hh++) {
        float2 pv = *(const float2*)(pe + hh * 512 + c0);
        float2 ov = make_float2(o[hh][0] + pv.x, o[hh][1] + pv.y);
        *(float2*)(dst + hh * 512 + c0) = ov;
    }
}

// ---------------------------------------------------------------------------
extern "C" void kernel_launch(void* const* d_in, const int* in_sizes, int n_in,
                              void* d_out, int out_size) {
    (void)in_sizes; (void)n_in; (void)out_size;

    ConvParams P;
    P.x = (const float*)d_in[0];
    for (int i = 0; i < 4; i++) {
        P.w[i]     = (const float*)d_in[1 + i * 5 + 0];
        P.gamma[i] = (const float*)d_in[1 + i * 5 + 1];
        P.beta[i]  = (const float*)d_in[1 + i * 5 + 2];
        P.mean[i]  = (const float*)d_in[1 + i * 5 + 3];
        P.var[i]   = (const float*)d_in[1 + i * 5 + 4];
    }

    const int CONV_SMEM = (32 * 520 + 32 * 32 * 4 + 32 * 32 + 64) * 4;   // 87296 B
    const int ATTN_SMEM = (3 * 8192 + 32 * 512) * 4;                     // 163840 B
    cudaFuncSetAttribute(conv_kernel, cudaFuncAttributeMaxDynamicSharedMemorySize, CONV_SMEM);
    cudaFuncSetAttribute(attn_kernel, cudaFuncAttributeMaxDynamicSharedMemorySize, ATTN_SMEM);

    conv_kernel<<<dim3(8, 16, 16), 256, CONV_SMEM>>>(P);
    attn_kernel<<<1024, 256, ATTN_SMEM>>>((float*)d_out);
}

// round 4
// speedup vs baseline: 1.2171x; 1.2171x over previous
#include <cuda_runtime.h>

#define LRELU_SLOPE 0.3f
#define BN_EPS 1e-5f

// Scratch: [t][b][c][h][w] : 4 x 16 x 64 x 16 x 512 floats = 134 MB
__device__ float g_qkvp[4u * 16u * 64u * 16u * 512u];

typedef unsigned long long ull;

__device__ __forceinline__ ull ffma2(ull a, ull b, ull c) {
    ull d;
    asm("fma.rn.f32x2 %0, %1, %2, %3;" : "=l"(d) : "l"(a), "l"(b), "l"(c));
    return d;
}
__device__ __forceinline__ ull dup2(float x) {
    ull d;
    asm("mov.b64 %0, {%1, %1};" : "=l"(d) : "r"(__float_as_uint(x)));
    return d;
}
__device__ __forceinline__ void unpack2(ull v, float& lo, float& hi) {
    unsigned l, h;
    asm("mov.b64 {%0, %1}, %2;" : "=r"(l), "=r"(h) : "l"(v));
    lo = __uint_as_float(l);
    hi = __uint_as_float(h);
}

struct ConvParams {
    const float* x;
    const float* w[4];
    const float* gamma[4];
    const float* beta[4];
    const float* mean[4];
    const float* var[4];
};

// ---------------------------------------------------------------------------
// Conv(1,5) + folded BN + LeakyReLU for all 4 branches, FFMA2-packed over
// output-channel pairs.
// grid (8, 16, 16) = (tc-group of 32, h, b); 256 threads.
// Thread tile: 4 consecutive w  x  16 (t,c) outputs (8 channel-pairs).
// ---------------------------------------------------------------------------
__global__ void __launch_bounds__(256, 1) conv_kernel(ConvParams P) {
    extern __shared__ float sm[];
    float* xs     = sm;                    // 32 * 520 (x row, +2 halo at idx 0..1)
    float* wp     = xs + 32 * 520;         // 2 grp * 8 pair * 32 ci * 12 floats
    float* sscale = wp + 2 * 8 * 32 * 12;  // 32
    float* sshift = sscale + 32;           // 32

    const int s   = blockIdx.x;   // tc group
    const int h   = blockIdx.y;
    const int b   = blockIdx.z;
    const int tid = threadIdx.x;
    const int tcbase = s * 32;

    // BN scale/shift per (t,c)
    if (tid < 32) {
        int tc = tcbase + tid;
        int t = tc >> 6, c = tc & 63;
        float sc = P.gamma[t][c] * rsqrtf(P.var[t][c] + BN_EPS);
        sscale[tid] = sc;
        sshift[tid] = P.beta[t][c] - P.mean[t][c] * sc;
    }
    __syncthreads();

    // Fold scale into weights; interleave channel pairs: slot (g,p,ci) holds
    // taps t=0..4 as float2 (w[j0][t]*sc0, w[j1][t]*sc1), j0 = g*16+2p.
    for (int e = tid; e < 512; e += 256) {
        int g = e >> 8, rem = e & 255;
        int p = rem >> 5, ci = rem & 31;
        int j0 = g * 16 + 2 * p;
        int tc0 = tcbase + j0, tc1 = tc0 + 1;
        int t0 = tc0 >> 6, c0 = tc0 & 63;
        int t1 = tc1 >> 6, c1 = tc1 & 63;
        const float* s0 = P.w[t0] + (c0 * 32 + ci) * 5;
        const float* s1 = P.w[t1] + (c1 * 32 + ci) * 5;
        float sc0 = sscale[j0], sc1 = sscale[j0 + 1];
        float* dst = wp + ((g * 8 + p) * 32 + ci) * 12;
#pragma unroll
        for (int t = 0; t < 5; t++) {
            dst[2 * t]     = s0[t] * sc0;
            dst[2 * t + 1] = s1[t] * sc1;
        }
    }

    // Stage x row: xs[ci*520 + 2 + w]; halos zero.
    for (int it = 0; it < 16; it++) {
        int li = it * 1024 + tid * 4;     // over 32*512
        int ci = li >> 9, w = li & 511;
        float4 v = *(const float4*)(P.x + ((b * 32 + ci) * 16 + h) * 512 + w);
        float* d = xs + ci * 520 + 2 + w;
        d[0] = v.x; d[1] = v.y; d[2] = v.z; d[3] = v.w;
    }
    if (tid < 64) {
        int ci = tid >> 1, pp = tid & 1;
        xs[ci * 520 + pp]       = 0.0f;
        xs[ci * 520 + 514 + pp] = 0.0f;
    }
    __syncthreads();

    const int lane = tid & 31, ww = tid >> 5;
    const int wseg = ww & 3;
    const int g    = ww >> 2;             // 0 or 1 -> local tc base g*16
    const int wb   = wseg * 128 + lane * 4;

    ull acc2[8][4];
    const ull z = dup2(0.0f);
#pragma unroll
    for (int p = 0; p < 8; p++)
#pragma unroll
        for (int u = 0; u < 4; u++) acc2[p][u] = z;

#pragma unroll 2
    for (int ci = 0; ci < 32; ci++) {
        const float* xr = xs + ci * 520 + wb;   // xr[0] == x[wb-2]
        float4 xa = *(const float4*)xr;
        float4 xb = *(const float4*)(xr + 4);
        ull xd[8];
        xd[0] = dup2(xa.x); xd[1] = dup2(xa.y); xd[2] = dup2(xa.z); xd[3] = dup2(xa.w);
        xd[4] = dup2(xb.x); xd[5] = dup2(xb.y); xd[6] = dup2(xb.z); xd[7] = dup2(xb.w);
        const float* wrow = wp + (g * 8 * 32 + ci) * 12;
#pragma unroll
        for (int p = 0; p < 8; p++) {
            const float* wq = wrow + p * 32 * 12;
            ulonglong2 w01 = *(const ulonglong2*)wq;        // taps 0,1
            ulonglong2 w23 = *(const ulonglong2*)(wq + 4);  // taps 2,3
            ull        w4p = *(const ull*)(wq + 8);         // tap 4
#pragma unroll
            for (int u = 0; u < 4; u++) {
                ull a = acc2[p][u];
                a = ffma2(xd[u],     w01.x, a);
                a = ffma2(xd[u + 1], w01.y, a);
                a = ffma2(xd[u + 2], w23.x, a);
                a = ffma2(xd[u + 3], w23.y, a);
                a = ffma2(xd[u + 4], w4p,   a);
                acc2[p][u] = a;
            }
        }
    }

#pragma unroll
    for (int p = 0; p < 8; p++) {
        int j0 = g * 16 + 2 * p;
        float sh0 = sshift[j0], sh1 = sshift[j0 + 1];
        float r0[4], r1[4];
#pragma unroll
        for (int u = 0; u < 4; u++) {
            float v0, v1;
            unpack2(acc2[p][u], v0, v1);
            v0 += sh0; v1 += sh1;
            r0[u] = (v0 >= 0.0f) ? v0 : LRELU_SLOPE * v0;
            r1[u] = (v1 >= 0.0f) ? v1 : LRELU_SLOPE * v1;
        }
        int tc0 = tcbase + j0;
        int t0 = tc0 >> 6, c0 = tc0 & 63;
        int t1 = (tc0 + 1) >> 6, c1 = (tc0 + 1) & 63;
        *(float4*)(g_qkvp + (size_t)(((t0 * 16 + b) * 64 + c0) * 16 + h) * 512 + wb) =
            make_float4(r0[0], r0[1], r0[2], r0[3]);
        *(float4*)(g_qkvp + (size_t)(((t1 * 16 + b) * 64 + c1) * 16 + h) * 512 + wb) =
            make_float4(r1[0], r1[1], r1[2], r1[3]);
    }
}

// ---------------------------------------------------------------------------
// Attention per (b,c):  A = Q^T K (512x512, K=16), softmax rows,
// O = V @ A (16x512, K=512) + PE.  FFMA2-packed both GEMMs.
// 1024 CTAs, 512 threads, 224 KB dynamic SMEM (row-block of 64).
// ---------------------------------------------------------------------------
__global__ void __launch_bounds__(512, 1) attn_kernel(float* __restrict__ out) {
    extern __shared__ float sm[];
    float* Qs = sm;              // 16*512
    float* Ks = Qs + 8192;       // 16*512
    float* Vs = Ks + 8192;       // 16*512
    float* Ss = Vs + 8192;       // 64*512 (current softmaxed row block)

    const int bc   = blockIdx.x;           // b*64 + c
    const int tid  = threadIdx.x;
    const int lane = tid & 31, ww = tid >> 5;

    // Stage Q, K, V
    {
        const float4* q = (const float4*)(g_qkvp + (size_t)(0 * 1024 + bc) * 8192);
        const float4* k = (const float4*)(g_qkvp + (size_t)(1 * 1024 + bc) * 8192);
        const float4* v = (const float4*)(g_qkvp + (size_t)(2 * 1024 + bc) * 8192);
        for (int i = tid; i < 2048; i += 512) {
            ((float4*)Qs)[i] = q[i];
            ((float4*)Ks)[i] = k[i];
            ((float4*)Vs)[i] = v[i];
        }
    }
    __syncthreads();

    // Phase-B thread tile: 4 h-rows x 4 columns
    const int hgrp = ww >> 2;              // 0..3 -> h rows hgrp*4..+4
    const int cseg = ww & 3;
    const int c0   = cseg * 128 + lane * 4;

    ull o2[4][2];
    const ull z = dup2(0.0f);
#pragma unroll
    for (int hh = 0; hh < 4; hh++) { o2[hh][0] = z; o2[hh][1] = z; }

    for (int blk = 0; blk < 8; blk++) {
        // ---- Phase A: warp ww computes softmax rows r0..r0+3 ----
        ull a2[4][8];
#pragma unroll
        for (int r = 0; r < 4; r++)
#pragma unroll
            for (int j = 0; j < 8; j++) a2[r][j] = z;

        const int r0 = blk * 64 + ww * 4;
#pragma unroll 1
        for (int h = 0; h < 16; h++) {
            float4 qv = *(const float4*)(Qs + h * 512 + r0);
            ull qd[4];
            qd[0] = dup2(qv.x); qd[1] = dup2(qv.y);
            qd[2] = dup2(qv.z); qd[3] = dup2(qv.w);
            const float* krow = Ks + h * 512 + lane * 4;
#pragma unroll
            for (int j4 = 0; j4 < 4; j4++) {
                ulonglong2 kv = *(const ulonglong2*)(krow + j4 * 128);
#pragma unroll
                for (int r = 0; r < 4; r++) {
                    a2[r][j4 * 2]     = ffma2(qd[r], kv.x, a2[r][j4 * 2]);
                    a2[r][j4 * 2 + 1] = ffma2(qd[r], kv.y, a2[r][j4 * 2 + 1]);
                }
            }
        }

#pragma unroll
        for (int r = 0; r < 4; r++) {
            float av[16];
#pragma unroll
            for (int j = 0; j < 8; j++) unpack2(a2[r][j], av[2 * j], av[2 * j + 1]);
            float m = av[0];
#pragma unroll
            for (int j = 1; j < 16; j++) m = fmaxf(m, av[j]);
#pragma unroll
            for (int off = 16; off > 0; off >>= 1)
                m = fmaxf(m, __shfl_xor_sync(0xffffffffu, m, off));
            float ssum = 0.0f;
#pragma unroll
            for (int j = 0; j < 16; j++) {
                float e = __expf(av[j] - m);
                av[j] = e;
                ssum += e;
            }
#pragma unroll
            for (int off = 16; off > 0; off >>= 1)
                ssum += __shfl_xor_sync(0xffffffffu, ssum, off);
            float inv = 1.0f / ssum;
            float* srow = Ss + (ww * 4 + r) * 512 + lane * 4;
#pragma unroll
            for (int j4 = 0; j4 < 4; j4++) {
                *(float4*)(srow + j4 * 128) =
                    make_float4(av[j4 * 4 + 0] * inv, av[j4 * 4 + 1] * inv,
                                av[j4 * 4 + 2] * inv, av[j4 * 4 + 3] * inv);
            }
        }
        __syncthreads();

        // ---- Phase B: accumulate O[hgrp*4..+4, c0..c0+3] over this block ----
#pragma unroll 2
        for (int w = 0; w < 64; w++) {
            int wg = blk * 64 + w;
            ulonglong2 pv = *(const ulonglong2*)(Ss + w * 512 + c0);
            const float* vcol = Vs + hgrp * 4 * 512 + wg;
#pragma unroll
            for (int hh = 0; hh < 4; hh++) {
                ull vd = dup2(vcol[hh * 512]);
                o2[hh][0] = ffma2(vd, pv.x, o2[hh][0]);
                o2[hh][1] = ffma2(vd, pv.y, o2[hh][1]);
            }
        }
        __syncthreads();   // protect Ss before next block overwrites it
    }

    // Epilogue: add PE, store
    const float* pe = g_qkvp + (size_t)(3 * 1024 + bc) * 8192;
    float* dst = out + (size_t)bc * 8192;
#pragma unroll
    for (int hh = 0; hh < 4; hh++) {
        int h = hgrp * 4 + hh;
        float4 pv = *(const float4*)(pe + h * 512 + c0);
        float v0, v1, v2, v3;
        unpack2(o2[hh][0], v0, v1);
        unpack2(o2[hh][1], v2, v3);
        *(float4*)(dst + h * 512 + c0) =
            make_float4(v0 + pv.x, v1 + pv.y, v2 + pv.z, v3 + pv.w);
    }
}

// ---------------------------------------------------------------------------
extern "C" void kernel_launch(void* const* d_in, const int* in_sizes, int n_in,
                              void* d_out, int out_size) {
    (void)in_sizes; (void)n_in; (void)out_size;

    ConvParams P;
    P.x = (const float*)d_in[0];
    for (int i = 0; i < 4; i++) {
        P.w[i]     = (const float*)d_in[1 + i * 5 + 0];
        P.gamma[i] = (const float*)d_in[1 + i * 5 + 1];
        P.beta[i]  = (const float*)d_in[1 + i * 5 + 2];
        P.mean[i]  = (const float*)d_in[1 + i * 5 + 3];
        P.var[i]   = (const float*)d_in[1 + i * 5 + 4];
    }

    const int CONV_SMEM = (32 * 520 + 2 * 8 * 32 * 12 + 64) * 4;   // 91392 B
    const int ATTN_SMEM = (3 * 8192 + 64 * 512) * 4;               // 229376 B
    cudaFuncSetAttribute(conv_kernel, cudaFuncAttributeMaxDynamicSharedMemorySize, CONV_SMEM);
    cudaFuncSetAttribute(attn_kernel, cudaFuncAttributeMaxDynamicSharedMemorySize, ATTN_SMEM);

    conv_kernel<<<dim3(8, 16, 16), 256, CONV_SMEM>>>(P);
    attn_kernel<<<1024, 512, ATTN_SMEM>>>((float*)d_out);
}

// round 6
// speedup vs baseline: 1.6706x; 1.3726x over previous
#include <cuda_runtime.h>

#define LRELU_SLOPE 0.3f
#define BN_EPS 1e-5f

// Scratch: [t][b][c][h][w] : 4 x 16 x 64 x 16 x 512 floats = 134 MB
__device__ float g_qkvp[4u * 16u * 64u * 16u * 512u];

typedef unsigned long long ull;

__device__ __forceinline__ ull ffma2(ull a, ull b, ull c) {
    ull d;
    asm("fma.rn.f32x2 %0, %1, %2, %3;" : "=l"(d) : "l"(a), "l"(b), "l"(c));
    return d;
}
__device__ __forceinline__ ull dup2(float x) {
    ull d;
    asm("mov.b64 %0, {%1, %1};" : "=l"(d) : "r"(__float_as_uint(x)));
    return d;
}
__device__ __forceinline__ void unpack2(ull v, float& lo, float& hi) {
    unsigned l, h;
    asm("mov.b64 {%0, %1}, %2;" : "=r"(l), "=r"(h) : "l"(v));
    lo = __uint_as_float(l);
    hi = __uint_as_float(h);
}

// round fp32 -> tf32 (result is an fp32 bit-pattern with low mantissa cleared)
__device__ __forceinline__ float to_tf32(float x) {
    unsigned u;
    asm("cvt.rna.tf32.f32 %0, %1;" : "=r"(u) : "f"(x));
    return __uint_as_float(u);
}

// D(16x8) += A(16x8,row) * B(8x8,col), tf32 inputs, fp32 accum
__device__ __forceinline__ void mma8(float* c, const unsigned* a, unsigned b0, unsigned b1) {
    asm volatile(
        "mma.sync.aligned.m16n8k8.row.col.f32.tf32.tf32.f32 "
        "{%0,%1,%2,%3}, {%4,%5,%6,%7}, {%8,%9}, {%0,%1,%2,%3};"
        : "+f"(c[0]), "+f"(c[1]), "+f"(c[2]), "+f"(c[3])
        : "r"(a[0]), "r"(a[1]), "r"(a[2]), "r"(a[3]), "r"(b0), "r"(b1));
}

struct ConvParams {
    const float* x;
    const float* w[4];
    const float* gamma[4];
    const float* beta[4];
    const float* mean[4];
    const float* var[4];
};

// ---------------------------------------------------------------------------
// Conv(1,5) + folded BN + LeakyReLU for all 4 branches, FFMA2-packed over
// output-channel pairs. grid (8, 16, 16); 256 threads.
// ---------------------------------------------------------------------------
__global__ void __launch_bounds__(256, 1) conv_kernel(ConvParams P) {
    extern __shared__ float sm[];
    float* xs     = sm;                    // 32 * 520
    float* wp     = xs + 32 * 520;         // 2 grp * 8 pair * 32 ci * 12
    float* sscale = wp + 2 * 8 * 32 * 12;  // 32
    float* sshift = sscale + 32;           // 32

    const int s   = blockIdx.x;
    const int h   = blockIdx.y;
    const int b   = blockIdx.z;
    const int tid = threadIdx.x;
    const int tcbase = s * 32;

    if (tid < 32) {
        int tc = tcbase + tid;
        int t = tc >> 6, c = tc & 63;
        float sc = P.gamma[t][c] * rsqrtf(P.var[t][c] + BN_EPS);
        sscale[tid] = sc;
        sshift[tid] = P.beta[t][c] - P.mean[t][c] * sc;
    }
    __syncthreads();

    for (int e = tid; e < 512; e += 256) {
        int g = e >> 8, rem = e & 255;
        int p = rem >> 5, ci = rem & 31;
        int j0 = g * 16 + 2 * p;
        int tc0 = tcbase + j0, tc1 = tc0 + 1;
        int t0 = tc0 >> 6, c0 = tc0 & 63;
        int t1 = tc1 >> 6, c1 = tc1 & 63;
        const float* s0 = P.w[t0] + (c0 * 32 + ci) * 5;
        const float* s1 = P.w[t1] + (c1 * 32 + ci) * 5;
        float sc0 = sscale[j0], sc1 = sscale[j0 + 1];
        float* dst = wp + ((g * 8 + p) * 32 + ci) * 12;
#pragma unroll
        for (int t = 0; t < 5; t++) {
            dst[2 * t]     = s0[t] * sc0;
            dst[2 * t + 1] = s1[t] * sc1;
        }
    }

    for (int it = 0; it < 16; it++) {
        int li = it * 1024 + tid * 4;
        int ci = li >> 9, w = li & 511;
        float4 v = *(const float4*)(P.x + ((b * 32 + ci) * 16 + h) * 512 + w);
        float* d = xs + ci * 520 + 2 + w;
        d[0] = v.x; d[1] = v.y; d[2] = v.z; d[3] = v.w;
    }
    if (tid < 64) {
        int ci = tid >> 1, pp = tid & 1;
        xs[ci * 520 + pp]       = 0.0f;
        xs[ci * 520 + 514 + pp] = 0.0f;
    }
    __syncthreads();

    const int lane = tid & 31, ww = tid >> 5;
    const int wseg = ww & 3;
    const int g    = ww >> 2;
    const int wb   = wseg * 128 + lane * 4;

    ull acc2[8][4];
    const ull z = dup2(0.0f);
#pragma unroll
    for (int p = 0; p < 8; p++)
#pragma unroll
        for (int u = 0; u < 4; u++) acc2[p][u] = z;

#pragma unroll 2
    for (int ci = 0; ci < 32; ci++) {
        const float* xr = xs + ci * 520 + wb;
        float4 xa = *(const float4*)xr;
        float4 xb = *(const float4*)(xr + 4);
        ull xd[8];
        xd[0] = dup2(xa.x); xd[1] = dup2(xa.y); xd[2] = dup2(xa.z); xd[3] = dup2(xa.w);
        xd[4] = dup2(xb.x); xd[5] = dup2(xb.y); xd[6] = dup2(xb.z); xd[7] = dup2(xb.w);
        const float* wrow = wp + (g * 8 * 32 + ci) * 12;
#pragma unroll
        for (int p = 0; p < 8; p++) {
            const float* wq = wrow + p * 32 * 12;
            ulonglong2 w01 = *(const ulonglong2*)wq;
            ulonglong2 w23 = *(const ulonglong2*)(wq + 4);
            ull        w4p = *(const ull*)(wq + 8);
#pragma unroll
            for (int u = 0; u < 4; u++) {
                ull a = acc2[p][u];
                a = ffma2(xd[u],     w01.x, a);
                a = ffma2(xd[u + 1], w01.y, a);
                a = ffma2(xd[u + 2], w23.x, a);
                a = ffma2(xd[u + 3], w23.y, a);
                a = ffma2(xd[u + 4], w4p,   a);
                acc2[p][u] = a;
            }
        }
    }

#pragma unroll
    for (int p = 0; p < 8; p++) {
        int j0 = g * 16 + 2 * p;
        float sh0 = sshift[j0], sh1 = sshift[j0 + 1];
        float r0[4], r1[4];
#pragma unroll
        for (int u = 0; u < 4; u++) {
            float v0, v1;
            unpack2(acc2[p][u], v0, v1);
            v0 += sh0; v1 += sh1;
            r0[u] = (v0 >= 0.0f) ? v0 : LRELU_SLOPE * v0;
            r1[u] = (v1 >= 0.0f) ? v1 : LRELU_SLOPE * v1;
        }
        int tc0 = tcbase + j0;
        int t0 = tc0 >> 6, c0 = tc0 & 63;
        int t1 = (tc0 + 1) >> 6, c1 = (tc0 + 1) & 63;
        *(float4*)(g_qkvp + (size_t)(((t0 * 16 + b) * 64 + c0) * 16 + h) * 512 + wb) =
            make_float4(r0[0], r0[1], r0[2], r0[3]);
        *(float4*)(g_qkvp + (size_t)(((t1 * 16 + b) * 64 + c1) * 16 + h) * 512 + wb) =
            make_float4(r1[0], r1[1], r1[2], r1[3]);
    }
}

// ---------------------------------------------------------------------------
// Attention per (b,c) via tf32 mma.sync:
//   L = Q^T K (512x512, K=16) in 64-row blocks; softmax rows; O += V @ P.
// 1024 CTAs, 512 threads (16 warps), SMEM 231680 B.
// Warp layout Phase A: warp = (m-tile wp>>2) x (n-chunk (wp&3)*128).
// Warp layout Phase B: warp wp owns output n-columns [wp*32, wp*32+32).
// ---------------------------------------------------------------------------
#define QS_STR 516
#define KS_STR 520
#define VS_STR 520
#define SS_STR 516

__global__ void __launch_bounds__(512, 1) attn_kernel(float* __restrict__ out) {
    extern __shared__ float sm[];
    float* Qs  = sm;                     // 16 x 516  (Q as [h][w], tf32-rounded)
    float* Ks  = Qs + 16 * QS_STR;       // 16 x 520
    float* Vs  = Ks + 16 * KS_STR;       // 16 x 520
    float* Ss  = Vs + 16 * VS_STR;       // 64 x 516  (P block)
    float* red = Ss;                     // overlay [64][4] partial max/sum

    const int bc   = blockIdx.x;
    const int tid  = threadIdx.x;
    const int lane = tid & 31, wp = tid >> 5;
    const int g = lane >> 2, q = lane & 3;   // mma groupID / threadID-in-group

    // Stage + tf32-round Q, K, V
    {
        const float4* qg = (const float4*)(g_qkvp + (size_t)(0 * 1024 + bc) * 8192);
        const float4* kg = (const float4*)(g_qkvp + (size_t)(1 * 1024 + bc) * 8192);
        const float4* vg = (const float4*)(g_qkvp + (size_t)(2 * 1024 + bc) * 8192);
        for (int i = tid; i < 2048; i += 512) {
            int h = i >> 7, c = (i & 127) << 2;
            float4 a = qg[i];
            *(float4*)(Qs + h * QS_STR + c) =
                make_float4(to_tf32(a.x), to_tf32(a.y), to_tf32(a.z), to_tf32(a.w));
            float4 b = kg[i];
            *(float4*)(Ks + h * KS_STR + c) =
                make_float4(to_tf32(b.x), to_tf32(b.y), to_tf32(b.z), to_tf32(b.w));
            float4 v = vg[i];
            *(float4*)(Vs + h * VS_STR + c) =
                make_float4(to_tf32(v.x), to_tf32(v.y), to_tf32(v.z), to_tf32(v.w));
        }
    }
    __syncthreads();

    const int mt    = wp >> 2;          // Phase A m-tile (0..3)
    const int chunk = wp & 3;           // Phase A n-chunk (0..3)
    const int nb    = chunk * 128;
    const int m0    = mt * 16;
    const int rowA  = m0 + g;           // block-local logit rows (and rowA+8)

    float O[4][4];
#pragma unroll
    for (int t = 0; t < 4; t++)
#pragma unroll
        for (int u = 0; u < 4; u++) O[t][u] = 0.0f;

    for (int blk = 0; blk < 8; blk++) {
        // ---- Phase A: logits L (m16 x n128 per warp) via mma ----
        float L[16][4];
#pragma unroll
        for (int t = 0; t < 16; t++)
#pragma unroll
            for (int u = 0; u < 4; u++) L[t][u] = 0.0f;

        const int wrow = blk * 64 + rowA;   // global w index of logit row
#pragma unroll
        for (int ks = 0; ks < 2; ks++) {
            int h0 = ks * 8;
            unsigned a[4];
            a[0] = __float_as_uint(Qs[(h0 + q) * QS_STR + wrow]);
            a[1] = __float_as_uint(Qs[(h0 + q) * QS_STR + wrow + 8]);
            a[2] = __float_as_uint(Qs[(h0 + q + 4) * QS_STR + wrow]);
            a[3] = __float_as_uint(Qs[(h0 + q + 4) * QS_STR + wrow + 8]);
#pragma unroll
            for (int t = 0; t < 16; t++) {
                int n0 = nb + t * 8;
                unsigned b0 = __float_as_uint(Ks[(h0 + q) * KS_STR + n0 + g]);
                unsigned b1 = __float_as_uint(Ks[(h0 + q + 4) * KS_STR + n0 + g]);
                mma8(L[t], a, b0, b1);
            }
        }

        // ---- softmax over full rows (cross-warp via red[]) ----
        float mA = -1e30f, mB = -1e30f;
#pragma unroll
        for (int t = 0; t < 16; t++) {
            mA = fmaxf(mA, fmaxf(L[t][0], L[t][1]));
            mB = fmaxf(mB, fmaxf(L[t][2], L[t][3]));
        }
        mA = fmaxf(mA, __shfl_xor_sync(0xffffffffu, mA, 1));
        mA = fmaxf(mA, __shfl_xor_sync(0xffffffffu, mA, 2));
        mB = fmaxf(mB, __shfl_xor_sync(0xffffffffu, mB, 1));
        mB = fmaxf(mB, __shfl_xor_sync(0xffffffffu, mB, 2));
        if (q == 0) {
            red[rowA * 4 + chunk]       = mA;
            red[(rowA + 8) * 4 + chunk] = mB;
        }
        __syncthreads();
        {
            float4 fA = *(const float4*)(red + rowA * 4);
            mA = fmaxf(fmaxf(fA.x, fA.y), fmaxf(fA.z, fA.w));
            float4 fB = *(const float4*)(red + (rowA + 8) * 4);
            mB = fmaxf(fmaxf(fB.x, fB.y), fmaxf(fB.z, fB.w));
        }
        float sA = 0.0f, sB = 0.0f;
#pragma unroll
        for (int t = 0; t < 16; t++) {
            float e0 = __expf(L[t][0] - mA); L[t][0] = e0; sA += e0;
            float e1 = __expf(L[t][1] - mA); L[t][1] = e1; sA += e1;
            float e2 = __expf(L[t][2] - mB); L[t][2] = e2; sB += e2;
            float e3 = __expf(L[t][3] - mB); L[t][3] = e3; sB += e3;
        }
        sA += __shfl_xor_sync(0xffffffffu, sA, 1);
        sA += __shfl_xor_sync(0xffffffffu, sA, 2);
        sB += __shfl_xor_sync(0xffffffffu, sB, 1);
        sB += __shfl_xor_sync(0xffffffffu, sB, 2);
        __syncthreads();               // maxes consumed
        if (q == 0) {
            red[rowA * 4 + chunk]       = sA;
            red[(rowA + 8) * 4 + chunk] = sB;
        }
        __syncthreads();
        float invA, invB;
        {
            float4 fA = *(const float4*)(red + rowA * 4);
            invA = 1.0f / (fA.x + fA.y + fA.z + fA.w);
            float4 fB = *(const float4*)(red + (rowA + 8) * 4);
            invB = 1.0f / (fB.x + fB.y + fB.z + fB.w);
        }
        __syncthreads();               // red done -> Ss writable

        // ---- store P block (tf32-rounded) ----
#pragma unroll
        for (int t = 0; t < 16; t++) {
            int n0 = nb + t * 8 + 2 * q;
            *(float2*)(Ss + rowA * SS_STR + n0) =
                make_float2(to_tf32(L[t][0] * invA), to_tf32(L[t][1] * invA));
            *(float2*)(Ss + (rowA + 8) * SS_STR + n0) =
                make_float2(to_tf32(L[t][2] * invB), to_tf32(L[t][3] * invB));
        }
        __syncthreads();               // P visible

        // ---- Phase B: O(16 x n32 per warp) += V[:, blk] @ P ----
#pragma unroll
        for (int ks = 0; ks < 8; ks++) {
            int k0 = ks * 8;
            int kgl = blk * 64 + k0;
            unsigned a[4];
            a[0] = __float_as_uint(Vs[g * VS_STR + kgl + q]);
            a[1] = __float_as_uint(Vs[(g + 8) * VS_STR + kgl + q]);
            a[2] = __float_as_uint(Vs[g * VS_STR + kgl + q + 4]);
            a[3] = __float_as_uint(Vs[(g + 8) * VS_STR + kgl + q + 4]);
#pragma unroll
            for (int t = 0; t < 4; t++) {
                int n0 = wp * 32 + t * 8;
                unsigned b0 = __float_as_uint(Ss[(k0 + q) * SS_STR + n0 + g]);
                unsigned b1 = __float_as_uint(Ss[(k0 + q + 4) * SS_STR + n0 + g]);
                mma8(O[t], a, b0, b1);
            }
        }
        __syncthreads();               // Ss reusable next block
    }

    // ---- epilogue: + PE, store ----
    const float* pe = g_qkvp + (size_t)(3 * 1024 + bc) * 8192;
    float* dst = out + (size_t)bc * 8192;
#pragma unroll
    for (int t = 0; t < 4; t++) {
        int col = wp * 32 + t * 8 + 2 * q;
        float2 pA = *(const float2*)(pe + g * 512 + col);
        float2 pB = *(const float2*)(pe + (g + 8) * 512 + col);
        *(float2*)(dst + g * 512 + col) =
            make_float2(O[t][0] + pA.x, O[t][1] + pA.y);
        *(float2*)(dst + (g + 8) * 512 + col) =
            make_float2(O[t][2] + pB.x, O[t][3] + pB.y);
    }
}

// ---------------------------------------------------------------------------
extern "C" void kernel_launch(void* const* d_in, const int* in_sizes, int n_in,
                              void* d_out, int out_size) {
    (void)in_sizes; (void)n_in; (void)out_size;

    ConvParams P;
    P.x = (const float*)d_in[0];
    for (int i = 0; i < 4; i++) {
        P.w[i]     = (const float*)d_in[1 + i * 5 + 0];
        P.gamma[i] = (const float*)d_in[1 + i * 5 + 1];
        P.beta[i]  = (const float*)d_in[1 + i * 5 + 2];
        P.mean[i]  = (const float*)d_in[1 + i * 5 + 3];
        P.var[i]   = (const float*)d_in[1 + i * 5 + 4];
    }

    const int CONV_SMEM = (32 * 520 + 2 * 8 * 32 * 12 + 64) * 4;           // 91392 B
    const int ATTN_SMEM = (16 * QS_STR + 16 * KS_STR + 16 * VS_STR + 64 * SS_STR) * 4; // 231680 B
    cudaFuncSetAttribute(conv_kernel, cudaFuncAttributeMaxDynamicSharedMemorySize, CONV_SMEM);
    cudaFuncSetAttribute(attn_kernel, cudaFuncAttributeMaxDynamicSharedMemorySize, ATTN_SMEM);

    conv_kernel<<<dim3(8, 16, 16), 256, CONV_SMEM>>>(P);
    attn_kernel<<<1024, 512, ATTN_SMEM>>>((float*)d_out);
}

// round 7
// speedup vs baseline: 1.9362x; 1.1590x over previous
#include <cuda_runtime.h>

#define LRELU_SLOPE 0.3f
#define BN_EPS 1e-5f
#define LOG2E 1.4426950408889634f

// Scratch: [t][b][c][h][w] : 4 x 16 x 64 x 16 x 512 floats = 134 MB
__device__ float g_qkvp[4u * 16u * 64u * 16u * 512u];

typedef unsigned long long ull;

__device__ __forceinline__ ull ffma2(ull a, ull b, ull c) {
    ull d;
    asm("fma.rn.f32x2 %0, %1, %2, %3;" : "=l"(d) : "l"(a), "l"(b), "l"(c));
    return d;
}
__device__ __forceinline__ ull dup2(float x) {
    ull d;
    asm("mov.b64 %0, {%1, %1};" : "=l"(d) : "r"(__float_as_uint(x)));
    return d;
}
__device__ __forceinline__ void unpack2(ull v, float& lo, float& hi) {
    unsigned l, h;
    asm("mov.b64 {%0, %1}, %2;" : "=r"(l), "=r"(h) : "l"(v));
    lo = __uint_as_float(l);
    hi = __uint_as_float(h);
}
__device__ __forceinline__ float to_tf32(float x) {
    unsigned u;
    asm("cvt.rna.tf32.f32 %0, %1;" : "=r"(u) : "f"(x));
    return __uint_as_float(u);
}
__device__ __forceinline__ float ex2(float x) {
    float y;
    asm("ex2.approx.f32 %0, %1;" : "=f"(y) : "f"(x));
    return y;
}
// D(16x8) += A(16x8,row) * B(8x8,col), tf32 inputs, fp32 accum
__device__ __forceinline__ void mma8(float* c, const unsigned* a, unsigned b0, unsigned b1) {
    asm volatile(
        "mma.sync.aligned.m16n8k8.row.col.f32.tf32.tf32.f32 "
        "{%0,%1,%2,%3}, {%4,%5,%6,%7}, {%8,%9}, {%0,%1,%2,%3};"
        : "+f"(c[0]), "+f"(c[1]), "+f"(c[2]), "+f"(c[3])
        : "r"(a[0]), "r"(a[1]), "r"(a[2]), "r"(a[3]), "r"(b0), "r"(b1));
}
// fragment-plane index (float2 units): conflict-free for frag reads AND staging writes
__device__ __forceinline__ int Fidx(int w, int q) {
    return (w << 2) + (q ^ ((w >> 2) & 3));
}

struct ConvParams {
    const float* x;
    const float* w[4];
    const float* gamma[4];
    const float* beta[4];
    const float* mean[4];
    const float* var[4];
};

// ---------------------------------------------------------------------------
// Conv(1,5) + folded BN + LeakyReLU, FFMA2-packed. grid (8,16,16); 256 thr.
// ---------------------------------------------------------------------------
__global__ void __launch_bounds__(256, 2) conv_kernel(ConvParams P) {
    extern __shared__ float sm[];
    float* xs     = sm;                    // 32 * 520
    float* wp     = xs + 32 * 520;         // 2 grp * 8 pair * 32 ci * 12
    float* sscale = wp + 2 * 8 * 32 * 12;  // 32
    float* sshift = sscale + 32;           // 32

    const int s   = blockIdx.x;
    const int h   = blockIdx.y;
    const int b   = blockIdx.z;
    const int tid = threadIdx.x;
    const int tcbase = s * 32;

    if (tid < 32) {
        int tc = tcbase + tid;
        int t = tc >> 6, c = tc & 63;
        float sc = P.gamma[t][c] * rsqrtf(P.var[t][c] + BN_EPS);
        sscale[tid] = sc;
        sshift[tid] = P.beta[t][c] - P.mean[t][c] * sc;
    }
    __syncthreads();

    for (int e = tid; e < 512; e += 256) {
        int g = e >> 8, rem = e & 255;
        int p = rem >> 5, ci = rem & 31;
        int j0 = g * 16 + 2 * p;
        int tc0 = tcbase + j0, tc1 = tc0 + 1;
        int t0 = tc0 >> 6, c0 = tc0 & 63;
        int t1 = tc1 >> 6, c1 = tc1 & 63;
        const float* s0 = P.w[t0] + (c0 * 32 + ci) * 5;
        const float* s1 = P.w[t1] + (c1 * 32 + ci) * 5;
        float sc0 = sscale[j0], sc1 = sscale[j0 + 1];
        float* dst = wp + ((g * 8 + p) * 32 + ci) * 12;
#pragma unroll
        for (int t = 0; t < 5; t++) {
            dst[2 * t]     = s0[t] * sc0;
            dst[2 * t + 1] = s1[t] * sc1;
        }
    }

    for (int it = 0; it < 16; it++) {
        int li = it * 1024 + tid * 4;
        int ci = li >> 9, w = li & 511;
        float4 v = *(const float4*)(P.x + ((b * 32 + ci) * 16 + h) * 512 + w);
        float* d = xs + ci * 520 + 2 + w;
        d[0] = v.x; d[1] = v.y; d[2] = v.z; d[3] = v.w;
    }
    if (tid < 64) {
        int ci = tid >> 1, pp = tid & 1;
        xs[ci * 520 + pp]       = 0.0f;
        xs[ci * 520 + 514 + pp] = 0.0f;
    }
    __syncthreads();

    const int lane = tid & 31, ww = tid >> 5;
    const int wseg = ww & 3;
    const int g    = ww >> 2;
    const int wb   = wseg * 128 + lane * 4;

    ull acc2[8][4];
    const ull z = dup2(0.0f);
#pragma unroll
    for (int p = 0; p < 8; p++)
#pragma unroll
        for (int u = 0; u < 4; u++) acc2[p][u] = z;

#pragma unroll 2
    for (int ci = 0; ci < 32; ci++) {
        const float* xr = xs + ci * 520 + wb;
        float4 xa = *(const float4*)xr;
        float4 xb = *(const float4*)(xr + 4);
        ull xd[8];
        xd[0] = dup2(xa.x); xd[1] = dup2(xa.y); xd[2] = dup2(xa.z); xd[3] = dup2(xa.w);
        xd[4] = dup2(xb.x); xd[5] = dup2(xb.y); xd[6] = dup2(xb.z); xd[7] = dup2(xb.w);
        const float* wrow = wp + (g * 8 * 32 + ci) * 12;
#pragma unroll
        for (int p = 0; p < 8; p++) {
            const float* wq = wrow + p * 32 * 12;
            ulonglong2 w01 = *(const ulonglong2*)wq;
            ulonglong2 w23 = *(const ulonglong2*)(wq + 4);
            ull        w4p = *(const ull*)(wq + 8);
#pragma unroll
            for (int u = 0; u < 4; u++) {
                ull a = acc2[p][u];
                a = ffma2(xd[u],     w01.x, a);
                a = ffma2(xd[u + 1], w01.y, a);
                a = ffma2(xd[u + 2], w23.x, a);
                a = ffma2(xd[u + 3], w23.y, a);
                a = ffma2(xd[u + 4], w4p,   a);
                acc2[p][u] = a;
            }
        }
    }

#pragma unroll
    for (int p = 0; p < 8; p++) {
        int j0 = g * 16 + 2 * p;
        float sh0 = sshift[j0], sh1 = sshift[j0 + 1];
        float r0[4], r1[4];
#pragma unroll
        for (int u = 0; u < 4; u++) {
            float v0, v1;
            unpack2(acc2[p][u], v0, v1);
            v0 += sh0; v1 += sh1;
            r0[u] = (v0 >= 0.0f) ? v0 : LRELU_SLOPE * v0;
            r1[u] = (v1 >= 0.0f) ? v1 : LRELU_SLOPE * v1;
        }
        int tc0 = tcbase + j0;
        int t0 = tc0 >> 6, c0 = tc0 & 63;
        int t1 = (tc0 + 1) >> 6, c1 = (tc0 + 1) & 63;
        *(float4*)(g_qkvp + (size_t)(((t0 * 16 + b) * 64 + c0) * 16 + h) * 512 + wb) =
            make_float4(r0[0], r0[1], r0[2], r0[3]);
        *(float4*)(g_qkvp + (size_t)(((t1 * 16 + b) * 64 + c1) * 16 + h) * 512 + wb) =
            make_float4(r1[0], r1[1], r1[2], r1[3]);
    }
}

// ---------------------------------------------------------------------------
// Attention per (b,c), tf32 mma, fragment-packed smem, max-free exp2 softmax.
// 1024 CTAs, 512 threads (16 warps), 230656 B smem.
// smem (floats): Qf[2][2048]f2 | Kf[2][2048]f2 | Vf[8][516]f2 | Pf[8][2048]f2 | red[64][4]
// ---------------------------------------------------------------------------
__global__ void __launch_bounds__(512, 1) attn_kernel(float* __restrict__ out) {
    extern __shared__ float sm[];
    float2* Qf2 = (float2*)sm;                 // 4096 f2
    float2* Kf2 = Qf2 + 4096;                  // 4096 f2
    float2* Vf2 = Kf2 + 4096;                  // 4128 f2 (8 rows, stride 516)
    float2* Pf2 = Vf2 + 4128;                  // 16384 f2
    float*  red = (float*)(Pf2 + 16384);       // 256 f

    const int bc   = blockIdx.x;
    const int tid  = threadIdx.x;
    const int lane = tid & 31, wp = tid >> 5;
    const int g = lane >> 2, q = lane & 3;

    // ---- Staging: build packed tf32 fragment planes (Q pre-scaled by log2e) ----
    {
        const float* qg = g_qkvp + (size_t)(0 * 1024 + bc) * 8192;
        const float* kg = g_qkvp + (size_t)(1 * 1024 + bc) * 8192;
        const float* vg = g_qkvp + (size_t)(2 * 1024 + bc) * 8192;
        const int w = tid & 511;
#pragma unroll
        for (int j = 0; j < 8; j++) {
            int ks = j >> 2, qq = j & 3;
            int h0 = ks * 8 + qq;
            float a0 = qg[h0 * 512 + w] * LOG2E;
            float a1 = qg[(h0 + 4) * 512 + w] * LOG2E;
            Qf2[ks * 2048 + Fidx(w, qq)] = make_float2(to_tf32(a0), to_tf32(a1));
            float k0 = kg[h0 * 512 + w];
            float k1 = kg[(h0 + 4) * 512 + w];
            Kf2[ks * 2048 + Fidx(w, qq)] = make_float2(to_tf32(k0), to_tf32(k1));
            float v0 = vg[j * 512 + w];
            float v1 = vg[(j + 8) * 512 + w];
            Vf2[j * 516 + w] = make_float2(to_tf32(v0), to_tf32(v1));
        }
    }
    __syncthreads();

    const int mt    = wp >> 2;               // Phase A m-tile
    const int chunk = wp & 3;                // Phase A n-chunk
    const int nb    = chunk * 128;
    const int m0    = mt * 16;
    const int lr1   = m0 + (g & 3) + ((g >> 2) << 3);  // block-local logit row
    const int lr2   = lr1 + 4;
    const int ksg   = 2 * mt + (g >> 2);     // P k-group this thread writes
    const int qq    = g & 3;

    // Precomputed swizzle bases
    const int gb = nb + g;
    const int veK = (gb >> 2) & 3;
    const float2* kE = Kf2 + gb * 4 + (q ^ veK);
    const float2* kO = Kf2 + (gb + 8) * 4 + (q ^ veK ^ 2);

    const int cb = nb + 2 * q;
    const int vpP = (cb >> 2) & 3;
    float2* pE = Pf2 + ksg * 2048 + cb * 4 + (qq ^ vpP);
    float2* pO = Pf2 + ksg * 2048 + (cb + 8) * 4 + (qq ^ vpP ^ 2);

    const int nb2 = wp * 32 + g;
    const int vqB = (nb2 >> 2) & 3;
    const float2* pbE = Pf2 + nb2 * 4 + (q ^ vqB);
    const float2* pbO = Pf2 + (nb2 + 8) * 4 + (q ^ vqB ^ 2);

    float O[4][4];
#pragma unroll
    for (int t = 0; t < 4; t++)
#pragma unroll
        for (int u = 0; u < 4; u++) O[t][u] = 0.0f;

    for (int blk = 0; blk < 8; blk++) {
        // ---- Phase A: logits (rows W(g)=blk*64+lr1, W+4) x 128 cols ----
        float L[16][4];
#pragma unroll
        for (int t = 0; t < 16; t++)
#pragma unroll
            for (int u = 0; u < 4; u++) L[t][u] = 0.0f;

        const int W1 = blk * 64 + lr1;
#pragma unroll
        for (int ks = 0; ks < 2; ks++) {
            float2 p0 = Qf2[ks * 2048 + Fidx(W1, q)];
            float2 p1 = Qf2[ks * 2048 + Fidx(W1 + 4, q)];
            unsigned a[4] = { __float_as_uint(p0.x), __float_as_uint(p1.x),
                              __float_as_uint(p0.y), __float_as_uint(p1.y) };
            const float2* ke = kE + ks * 2048;
            const float2* ko = kO + ks * 2048;
#pragma unroll
            for (int t2 = 0; t2 < 8; t2++) {
                float2 bE = ke[t2 * 64];
                float2 bO = ko[t2 * 64];
                mma8(L[2 * t2],     a, __float_as_uint(bE.x), __float_as_uint(bE.y));
                mma8(L[2 * t2 + 1], a, __float_as_uint(bO.x), __float_as_uint(bO.y));
            }
        }

        // ---- exp2 (no max pass; logits bounded) + row sums ----
        float sA = 0.0f, sB = 0.0f;
#pragma unroll
        for (int t = 0; t < 16; t++) {
            float e0 = ex2(L[t][0]); L[t][0] = e0;
            float e1 = ex2(L[t][1]); L[t][1] = e1; sA += e0 + e1;
            float e2 = ex2(L[t][2]); L[t][2] = e2;
            float e3 = ex2(L[t][3]); L[t][3] = e3; sB += e2 + e3;
        }
        sA += __shfl_xor_sync(0xffffffffu, sA, 1);
        sA += __shfl_xor_sync(0xffffffffu, sA, 2);
        sB += __shfl_xor_sync(0xffffffffu, sB, 1);
        sB += __shfl_xor_sync(0xffffffffu, sB, 2);
        if (q == 0) {
            red[lr1 * 4 + chunk] = sA;
            red[lr2 * 4 + chunk] = sB;
        }
        __syncthreads();

        float invA, invB;
        {
            float4 rA = *(const float4*)(red + lr1 * 4);
            invA = __fdividef(1.0f, rA.x + rA.y + rA.z + rA.w);
            float4 rB = *(const float4*)(red + lr2 * 4);
            invB = __fdividef(1.0f, rB.x + rB.y + rB.z + rB.w);
        }

        // ---- store P fragments (pair rows (r, r+4) live in this thread) ----
#pragma unroll
        for (int t2 = 0; t2 < 8; t2++) {
            float* e = (float*)(pE + t2 * 64);
            e[0] = to_tf32(L[2 * t2][0] * invA);
            e[1] = to_tf32(L[2 * t2][2] * invB);
            e[8] = to_tf32(L[2 * t2][1] * invA);
            e[9] = to_tf32(L[2 * t2][3] * invB);
            float* o = (float*)(pO + t2 * 64);
            o[0] = to_tf32(L[2 * t2 + 1][0] * invA);
            o[1] = to_tf32(L[2 * t2 + 1][2] * invB);
            o[8] = to_tf32(L[2 * t2 + 1][1] * invA);
            o[9] = to_tf32(L[2 * t2 + 1][3] * invB);
        }
        __syncthreads();

        // ---- Phase B: O(rows g,g+8; 32 cols per warp) += V @ P ----
#pragma unroll
        for (int ks = 0; ks < 8; ks++) {
            int w0 = blk * 64 + ks * 8;
            float2 va = Vf2[g * 516 + w0 + q];
            float2 vb = Vf2[g * 516 + w0 + q + 4];
            unsigned a[4] = { __float_as_uint(va.x), __float_as_uint(va.y),
                              __float_as_uint(vb.x), __float_as_uint(vb.y) };
            float2 b0 = pbE[ks * 2048];
            float2 b1 = pbO[ks * 2048];
            float2 b2 = pbE[ks * 2048 + 64];
            float2 b3 = pbO[ks * 2048 + 64];
            mma8(O[0], a, __float_as_uint(b0.x), __float_as_uint(b0.y));
            mma8(O[1], a, __float_as_uint(b1.x), __float_as_uint(b1.y));
            mma8(O[2], a, __float_as_uint(b2.x), __float_as_uint(b2.y));
            mma8(O[3], a, __float_as_uint(b3.x), __float_as_uint(b3.y));
        }
        __syncthreads();
    }

    // ---- epilogue: + PE, store ----
    const float* pe = g_qkvp + (size_t)(3 * 1024 + bc) * 8192;
    float* dst = out + (size_t)bc * 8192;
#pragma unroll
    for (int t = 0; t < 4; t++) {
        int col = wp * 32 + t * 8 + 2 * q;
        float2 pA = *(const float2*)(pe + g * 512 + col);
        float2 pB = *(const float2*)(pe + (g + 8) * 512 + col);
        *(float2*)(dst + g * 512 + col) =
            make_float2(O[t][0] + pA.x, O[t][1] + pA.y);
        *(float2*)(dst + (g + 8) * 512 + col) =
            make_float2(O[t][2] + pB.x, O[t][3] + pB.y);
    }
}

// ---------------------------------------------------------------------------
extern "C" void kernel_launch(void* const* d_in, const int* in_sizes, int n_in,
                              void* d_out, int out_size) {
    (void)in_sizes; (void)n_in; (void)out_size;

    ConvParams P;
    P.x = (const float*)d_in[0];
    for (int i = 0; i < 4; i++) {
        P.w[i]     = (const float*)d_in[1 + i * 5 + 0];
        P.gamma[i] = (const float*)d_in[1 + i * 5 + 1];
        P.beta[i]  = (const float*)d_in[1 + i * 5 + 2];
        P.mean[i]  = (const float*)d_in[1 + i * 5 + 3];
        P.var[i]   = (const float*)d_in[1 + i * 5 + 4];
    }

    const int CONV_SMEM = (32 * 520 + 2 * 8 * 32 * 12 + 64) * 4;             // 91392 B
    const int ATTN_SMEM = (4096 + 4096 + 4128 + 16384) * 8 + 256 * 4;        // 230656 B
    cudaFuncSetAttribute(conv_kernel, cudaFuncAttributeMaxDynamicSharedMemorySize, CONV_SMEM);
    cudaFuncSetAttribute(attn_kernel, cudaFuncAttributeMaxDynamicSharedMemorySize, ATTN_SMEM);

    conv_kernel<<<dim3(8, 16, 16), 256, CONV_SMEM>>>(P);
    attn_kernel<<<1024, 512, ATTN_SMEM>>>((float*)d_out);
}

// round 8
// speedup vs baseline: 2.4033x; 1.2412x over previous
#include <cuda_runtime.h>

#define LRELU_SLOPE 0.3f
#define BN_EPS 1e-5f
#define LOG2E 1.4426950408889634f

// Scratch: [t][b][c][h][w] : 4 x 16 x 64 x 16 x 512 floats = 134 MB
__device__ float g_qkvp[4u * 16u * 64u * 16u * 512u];
// Prepacked conv weight A-fragments: [co_tile 16][step 20][lane 32] float4
__device__ float4 g_wf[16 * 20 * 32];

typedef unsigned long long ull;

__device__ __forceinline__ float to_tf32(float x) {
    unsigned u;
    asm("cvt.rna.tf32.f32 %0, %1;" : "=r"(u) : "f"(x));
    return __uint_as_float(u);
}
__device__ __forceinline__ float ex2(float x) {
    float y;
    asm("ex2.approx.f32 %0, %1;" : "=f"(y) : "f"(x));
    return y;
}
// D(16x8) += A(16x8,row) * B(8x8,col), tf32 inputs, fp32 accum
__device__ __forceinline__ void mma8(float* c, const unsigned* a, unsigned b0, unsigned b1) {
    asm volatile(
        "mma.sync.aligned.m16n8k8.row.col.f32.tf32.tf32.f32 "
        "{%0,%1,%2,%3}, {%4,%5,%6,%7}, {%8,%9}, {%0,%1,%2,%3};"
        : "+f"(c[0]), "+f"(c[1]), "+f"(c[2]), "+f"(c[3])
        : "r"(a[0]), "r"(a[1]), "r"(a[2]), "r"(a[3]), "r"(b0), "r"(b1));
}
// fragment-plane index (float2 units): conflict-free for frag reads AND staging writes
__device__ __forceinline__ int Fidx(int w, int q) {
    return (w << 2) + (q ^ ((w >> 2) & 3));
}

struct ConvParams {
    const float* x;
    const float* w[4];
    const float* gamma[4];
    const float* beta[4];
    const float* mean[4];
    const float* var[4];
};

// ---------------------------------------------------------------------------
// Prepack: fold BN scale into W, tf32-round, store mma A-fragments so each
// thread's 4 frag values are one float4 at [ct][step][lane]. 10240 entries.
// step s = tap*4 + ci_octet.
// ---------------------------------------------------------------------------
__global__ void prepack_kernel(ConvParams P) {
    int idx = blockIdx.x * 256 + threadIdx.x;
    if (idx >= 16 * 20 * 32) return;
    int lane = idx & 31;
    int s    = (idx >> 5) % 20;
    int ct   = idx / (20 * 32);
    int g = lane >> 2, q = lane & 3;
    int tap = s >> 2, o = s & 3;
    int co0 = ct * 16 + g, co1 = co0 + 8;
    int ci0 = o * 8 + q, ci1 = ci0 + 4;
    int t0 = co0 >> 6, c0 = co0 & 63;
    int t1 = co1 >> 6, c1 = co1 & 63;
    float sc0 = P.gamma[t0][c0] * rsqrtf(P.var[t0][c0] + BN_EPS);
    float sc1 = P.gamma[t1][c1] * rsqrtf(P.var[t1][c1] + BN_EPS);
    float4 v;
    v.x = to_tf32(P.w[t0][(c0 * 32 + ci0) * 5 + tap] * sc0);
    v.y = to_tf32(P.w[t1][(c1 * 32 + ci0) * 5 + tap] * sc1);
    v.z = to_tf32(P.w[t0][(c0 * 32 + ci1) * 5 + tap] * sc0);
    v.w = to_tf32(P.w[t1][(c1 * 32 + ci1) * 5 + tap] * sc1);
    g_wf[idx] = v;
}

// ---------------------------------------------------------------------------
// Conv via tf32 mma: out[co, w] = sum_{tap,ci} Wt[co,ci] * x[ci, w+tap-2],
// co = 0..255 (4 branches x 64), per (b, h, 128-w chunk).
// grid (4, 16, 16); 512 threads = 16 warps; warp wp: co-tile [wp*16,+16) x 128 w.
// smem: xs[32][136] (tf32 x slice, +halo) | Wfs (prepacked frags, 160 KB).
// ---------------------------------------------------------------------------
__global__ void __launch_bounds__(512, 1) conv_mma_kernel(ConvParams P) {
    extern __shared__ float sm[];
    float*  xs  = sm;                         // 32 * 136 floats
    float4* Wfs = (float4*)(sm + 32 * 136);   // 16*20*32 float4

    const int nc = blockIdx.x;                // w chunk (0..3)
    const int h  = blockIdx.y;
    const int b  = blockIdx.z;
    const int tid = threadIdx.x;
    const int lane = tid & 31, wp = tid >> 5;
    const int g = lane >> 2, q = lane & 3;
    const int w0 = nc * 128;

    // Stage prepacked W fragments (coalesced)
    {
        const float4* src = g_wf;
#pragma unroll
        for (int i = 0; i < 20; i++)
            Wfs[i * 512 + tid] = src[i * 512 + tid];
    }
    // Stage x slice [32 ci][w0-2 .. w0+130), tf32-rounded, zero halo
    for (int i = tid; i < 32 * 132; i += 512) {
        int ci = i / 132, cc = i - ci * 132;
        int wg = w0 - 2 + cc;
        float v = 0.0f;
        if (wg >= 0 && wg < 512)
            v = to_tf32(P.x[((b * 32 + ci) * 16 + h) * 512 + wg]);
        xs[ci * 136 + cc] = v;
    }
    __syncthreads();

    float O[16][4];
#pragma unroll
    for (int j = 0; j < 16; j++)
#pragma unroll
        for (int u = 0; u < 4; u++) O[j][u] = 0.0f;

#pragma unroll 4
    for (int s = 0; s < 20; s++) {
        int tap = s >> 2, o = s & 3;
        float4 A = Wfs[(wp * 20 + s) * 32 + lane];
        unsigned a[4] = { __float_as_uint(A.x), __float_as_uint(A.y),
                          __float_as_uint(A.z), __float_as_uint(A.w) };
        const float* b0p = xs + (o * 8 + q) * 136 + g + tap;
        const float* b1p = b0p + 4 * 136;
#pragma unroll
        for (int j = 0; j < 16; j++) {
            mma8(O[j], a, __float_as_uint(b0p[j * 8]), __float_as_uint(b1p[j * 8]));
        }
    }

    // Epilogue: + BN shift, LeakyReLU, store rows co0 (=wp*16+g) and co0+8
    const int co0 = wp * 16 + g;
    const int t0 = co0 >> 6, c0 = co0 & 63;          // co0+8 stays in same branch
    const int c1 = (co0 + 8) & 63;
    float sA = P.gamma[t0][c0] * rsqrtf(P.var[t0][c0] + BN_EPS);
    float shift0 = P.beta[t0][c0] - P.mean[t0][c0] * sA;
    float sB = P.gamma[t0][c1] * rsqrtf(P.var[t0][c1] + BN_EPS);
    float shift1 = P.beta[t0][c1] - P.mean[t0][c1] * sB;

    float* r0 = g_qkvp + (size_t)(((t0 * 16 + b) * 64 + c0) * 16 + h) * 512 + w0 + 2 * q;
    float* r1 = g_qkvp + (size_t)(((t0 * 16 + b) * 64 + c1) * 16 + h) * 512 + w0 + 2 * q;
#pragma unroll
    for (int j = 0; j < 16; j++) {
        float v0 = O[j][0] + shift0, v1 = O[j][1] + shift0;
        float v2 = O[j][2] + shift1, v3 = O[j][3] + shift1;
        v0 = (v0 >= 0.0f) ? v0 : LRELU_SLOPE * v0;
        v1 = (v1 >= 0.0f) ? v1 : LRELU_SLOPE * v1;
        v2 = (v2 >= 0.0f) ? v2 : LRELU_SLOPE * v2;
        v3 = (v3 >= 0.0f) ? v3 : LRELU_SLOPE * v3;
        *(float2*)(r0 + j * 8) = make_float2(v0, v1);
        *(float2*)(r1 + j * 8) = make_float2(v2, v3);
    }
}

// ---------------------------------------------------------------------------
// Attention per (b,c), tf32 mma, fragment-packed smem, max-free exp2 softmax.
// 1024 CTAs, 512 threads (16 warps), 230656 B smem.  (unchanged from R7)
// ---------------------------------------------------------------------------
__global__ void __launch_bounds__(512, 1) attn_kernel(float* __restrict__ out) {
    extern __shared__ float sm[];
    float2* Qf2 = (float2*)sm;                 // 4096 f2
    float2* Kf2 = Qf2 + 4096;                  // 4096 f2
    float2* Vf2 = Kf2 + 4096;                  // 4128 f2 (8 rows, stride 516)
    float2* Pf2 = Vf2 + 4128;                  // 16384 f2
    float*  red = (float*)(Pf2 + 16384);       // 256 f

    const int bc   = blockIdx.x;
    const int tid  = threadIdx.x;
    const int lane = tid & 31, wp = tid >> 5;
    const int g = lane >> 2, q = lane & 3;

    // ---- Staging: build packed tf32 fragment planes (Q pre-scaled by log2e) ----
    {
        const float* qg = g_qkvp + (size_t)(0 * 1024 + bc) * 8192;
        const float* kg = g_qkvp + (size_t)(1 * 1024 + bc) * 8192;
        const float* vg = g_qkvp + (size_t)(2 * 1024 + bc) * 8192;
        const int w = tid & 511;
#pragma unroll
        for (int j = 0; j < 8; j++) {
            int ks = j >> 2, qq = j & 3;
            int h0 = ks * 8 + qq;
            float a0 = qg[h0 * 512 + w] * LOG2E;
            float a1 = qg[(h0 + 4) * 512 + w] * LOG2E;
            Qf2[ks * 2048 + Fidx(w, qq)] = make_float2(to_tf32(a0), to_tf32(a1));
            float k0 = kg[h0 * 512 + w];
            float k1 = kg[(h0 + 4) * 512 + w];
            Kf2[ks * 2048 + Fidx(w, qq)] = make_float2(to_tf32(k0), to_tf32(k1));
            float v0 = vg[j * 512 + w];
            float v1 = vg[(j + 8) * 512 + w];
            Vf2[j * 516 + w] = make_float2(to_tf32(v0), to_tf32(v1));
        }
    }
    __syncthreads();

    const int mt    = wp >> 2;
    const int chunk = wp & 3;
    const int nb    = chunk * 128;
    const int m0    = mt * 16;
    const int lr1   = m0 + (g & 3) + ((g >> 2) << 3);
    const int lr2   = lr1 + 4;
    const int ksg   = 2 * mt + (g >> 2);
    const int qq    = g & 3;

    const int gb = nb + g;
    const int veK = (gb >> 2) & 3;
    const float2* kE = Kf2 + gb * 4 + (q ^ veK);
    const float2* kO = Kf2 + (gb + 8) * 4 + (q ^ veK ^ 2);

    const int cb = nb + 2 * q;
    const int vpP = (cb >> 2) & 3;
    float2* pE = Pf2 + ksg * 2048 + cb * 4 + (qq ^ vpP);
    float2* pO = Pf2 + ksg * 2048 + (cb + 8) * 4 + (qq ^ vpP ^ 2);

    const int nb2 = wp * 32 + g;
    const int vqB = (nb2 >> 2) & 3;
    const float2* pbE = Pf2 + nb2 * 4 + (q ^ vqB);
    const float2* pbO = Pf2 + (nb2 + 8) * 4 + (q ^ vqB ^ 2);

    float O[4][4];
#pragma unroll
    for (int t = 0; t < 4; t++)
#pragma unroll
        for (int u = 0; u < 4; u++) O[t][u] = 0.0f;

    for (int blk = 0; blk < 8; blk++) {
        float L[16][4];
#pragma unroll
        for (int t = 0; t < 16; t++)
#pragma unroll
            for (int u = 0; u < 4; u++) L[t][u] = 0.0f;

        const int W1 = blk * 64 + lr1;
#pragma unroll
        for (int ks = 0; ks < 2; ks++) {
            float2 p0 = Qf2[ks * 2048 + Fidx(W1, q)];
            float2 p1 = Qf2[ks * 2048 + Fidx(W1 + 4, q)];
            unsigned a[4] = { __float_as_uint(p0.x), __float_as_uint(p1.x),
                              __float_as_uint(p0.y), __float_as_uint(p1.y) };
            const float2* ke = kE + ks * 2048;
            const float2* ko = kO + ks * 2048;
#pragma unroll
            for (int t2 = 0; t2 < 8; t2++) {
                float2 bE = ke[t2 * 64];
                float2 bO = ko[t2 * 64];
                mma8(L[2 * t2],     a, __float_as_uint(bE.x), __float_as_uint(bE.y));
                mma8(L[2 * t2 + 1], a, __float_as_uint(bO.x), __float_as_uint(bO.y));
            }
        }

        float sA = 0.0f, sB = 0.0f;
#pragma unroll
        for (int t = 0; t < 16; t++) {
            float e0 = ex2(L[t][0]); L[t][0] = e0;
            float e1 = ex2(L[t][1]); L[t][1] = e1; sA += e0 + e1;
            float e2 = ex2(L[t][2]); L[t][2] = e2;
            float e3 = ex2(L[t][3]); L[t][3] = e3; sB += e2 + e3;
        }
        sA += __shfl_xor_sync(0xffffffffu, sA, 1);
        sA += __shfl_xor_sync(0xffffffffu, sA, 2);
        sB += __shfl_xor_sync(0xffffffffu, sB, 1);
        sB += __shfl_xor_sync(0xffffffffu, sB, 2);
        if (q == 0) {
            red[lr1 * 4 + chunk] = sA;
            red[lr2 * 4 + chunk] = sB;
        }
        __syncthreads();

        float invA, invB;
        {
            float4 rA = *(const float4*)(red + lr1 * 4);
            invA = __fdividef(1.0f, rA.x + rA.y + rA.z + rA.w);
            float4 rB = *(const float4*)(red + lr2 * 4);
            invB = __fdividef(1.0f, rB.x + rB.y + rB.z + rB.w);
        }

#pragma unroll
        for (int t2 = 0; t2 < 8; t2++) {
            float* e = (float*)(pE + t2 * 64);
            e[0] = to_tf32(L[2 * t2][0] * invA);
            e[1] = to_tf32(L[2 * t2][2] * invB);
            e[8] = to_tf32(L[2 * t2][1] * invA);
            e[9] = to_tf32(L[2 * t2][3] * invB);
            float* o = (float*)(pO + t2 * 64);
            o[0] = to_tf32(L[2 * t2 + 1][0] * invA);
            o[1] = to_tf32(L[2 * t2 + 1][2] * invB);
            o[8] = to_tf32(L[2 * t2 + 1][1] * invA);
            o[9] = to_tf32(L[2 * t2 + 1][3] * invB);
        }
        __syncthreads();

#pragma unroll
        for (int ks = 0; ks < 8; ks++) {
            int w0 = blk * 64 + ks * 8;
            float2 va = Vf2[g * 516 + w0 + q];
            float2 vb = Vf2[g * 516 + w0 + q + 4];
            unsigned a[4] = { __float_as_uint(va.x), __float_as_uint(va.y),
                              __float_as_uint(vb.x), __float_as_uint(vb.y) };
            float2 b0 = pbE[ks * 2048];
            float2 b1 = pbO[ks * 2048];
            float2 b2 = pbE[ks * 2048 + 64];
            float2 b3 = pbO[ks * 2048 + 64];
            mma8(O[0], a, __float_as_uint(b0.x), __float_as_uint(b0.y));
            mma8(O[1], a, __float_as_uint(b1.x), __float_as_uint(b1.y));
            mma8(O[2], a, __float_as_uint(b2.x), __float_as_uint(b2.y));
            mma8(O[3], a, __float_as_uint(b3.x), __float_as_uint(b3.y));
        }
        __syncthreads();
    }

    const float* pe = g_qkvp + (size_t)(3 * 1024 + bc) * 8192;
    float* dst = out + (size_t)bc * 8192;
#pragma unroll
    for (int t = 0; t < 4; t++) {
        int col = wp * 32 + t * 8 + 2 * q;
        float2 pA = *(const float2*)(pe + g * 512 + col);
        float2 pB = *(const float2*)(pe + (g + 8) * 512 + col);
        *(float2*)(dst + g * 512 + col) =
            make_float2(O[t][0] + pA.x, O[t][1] + pA.y);
        *(float2*)(dst + (g + 8) * 512 + col) =
            make_float2(O[t][2] + pB.x, O[t][3] + pB.y);
    }
}

// ---------------------------------------------------------------------------
extern "C" void kernel_launch(void* const* d_in, const int* in_sizes, int n_in,
                              void* d_out, int out_size) {
    (void)in_sizes; (void)n_in; (void)out_size;

    ConvParams P;
    P.x = (const float*)d_in[0];
    for (int i = 0; i < 4; i++) {
        P.w[i]     = (const float*)d_in[1 + i * 5 + 0];
        P.gamma[i] = (const float*)d_in[1 + i * 5 + 1];
        P.beta[i]  = (const float*)d_in[1 + i * 5 + 2];
        P.mean[i]  = (const float*)d_in[1 + i * 5 + 3];
        P.var[i]   = (const float*)d_in[1 + i * 5 + 4];
    }

    const int CONV_SMEM = 32 * 136 * 4 + 16 * 20 * 32 * 16;                  // 181248 B
    const int ATTN_SMEM = (4096 + 4096 + 4128 + 16384) * 8 + 256 * 4;        // 230656 B
    cudaFuncSetAttribute(conv_mma_kernel, cudaFuncAttributeMaxDynamicSharedMemorySize, CONV_SMEM);
    cudaFuncSetAttribute(attn_kernel, cudaFuncAttributeMaxDynamicSharedMemorySize, ATTN_SMEM);

    prepack_kernel<<<40, 256>>>(P);
    conv_mma_kernel<<<dim3(4, 16, 16), 512, CONV_SMEM>>>(P);
    attn_kernel<<<1024, 512, ATTN_SMEM>>>((float*)d_out);
}

// round 9
// speedup vs baseline: 3.1425x; 1.3075x over previous
#include <cuda_runtime.h>
#include <cuda_fp16.h>

#define LRELU_SLOPE 0.3f
#define BN_EPS 1e-5f
#define LOG2E 1.4426950408889634f

// Scratch: [t][b][c][h][w] : 4 x 16 x 64 x 16 x 512 floats = 134 MB
__device__ float g_qkvp[4u * 16u * 64u * 16u * 512u];
// Prepacked conv weight A-fragments: [co_tile 16][step 20][lane 32] float4
__device__ float4 g_wf[16 * 20 * 32];

__device__ __forceinline__ float to_tf32(float x) {
    unsigned u;
    asm("cvt.rna.tf32.f32 %0, %1;" : "=r"(u) : "f"(x));
    return __uint_as_float(u);
}
__device__ __forceinline__ float ex2(float x) {
    float y;
    asm("ex2.approx.f32 %0, %1;" : "=f"(y) : "f"(x));
    return y;
}
// D(16x8) += A(16x8,row) * B(8x8,col), tf32 inputs, fp32 accum
__device__ __forceinline__ void mma8(float* c, const unsigned* a, unsigned b0, unsigned b1) {
    asm volatile(
        "mma.sync.aligned.m16n8k8.row.col.f32.tf32.tf32.f32 "
        "{%0,%1,%2,%3}, {%4,%5,%6,%7}, {%8,%9}, {%0,%1,%2,%3};"
        : "+f"(c[0]), "+f"(c[1]), "+f"(c[2]), "+f"(c[3])
        : "r"(a[0]), "r"(a[1]), "r"(a[2]), "r"(a[3]), "r"(b0), "r"(b1));
}
// D(16x8) += A(16x16,row,f16) * B(16x8,col,f16), fp32 accum
__device__ __forceinline__ void mma16h(float* c, const unsigned* a, unsigned b0, unsigned b1) {
    asm volatile(
        "mma.sync.aligned.m16n8k16.row.col.f32.f16.f16.f32 "
        "{%0,%1,%2,%3}, {%4,%5,%6,%7}, {%8,%9}, {%0,%1,%2,%3};"
        : "+f"(c[0]), "+f"(c[1]), "+f"(c[2]), "+f"(c[3])
        : "r"(a[0]), "r"(a[1]), "r"(a[2]), "r"(a[3]), "r"(b0), "r"(b1));
}
// fragment-plane index (float2 units)
__device__ __forceinline__ int Fidx(int w, int q) {
    return (w << 2) + (q ^ ((w >> 2) & 3));
}

struct ConvParams {
    const float* x;
    const float* w[4];
    const float* gamma[4];
    const float* beta[4];
    const float* mean[4];
    const float* var[4];
};

// ---------------------------------------------------------------------------
// Prepack: fold BN scale into W, tf32-round, store mma A-fragments.
// ---------------------------------------------------------------------------
__global__ void prepack_kernel(ConvParams P) {
    int idx = blockIdx.x * 256 + threadIdx.x;
    if (idx >= 16 * 20 * 32) return;
    int lane = idx & 31;
    int s    = (idx >> 5) % 20;
    int ct   = idx / (20 * 32);
    int g = lane >> 2, q = lane & 3;
    int tap = s >> 2, o = s & 3;
    int co0 = ct * 16 + g, co1 = co0 + 8;
    int ci0 = o * 8 + q, ci1 = ci0 + 4;
    int t0 = co0 >> 6, c0 = co0 & 63;
    int t1 = co1 >> 6, c1 = co1 & 63;
    float sc0 = P.gamma[t0][c0] * rsqrtf(P.var[t0][c0] + BN_EPS);
    float sc1 = P.gamma[t1][c1] * rsqrtf(P.var[t1][c1] + BN_EPS);
    float4 v;
    v.x = to_tf32(P.w[t0][(c0 * 32 + ci0) * 5 + tap] * sc0);
    v.y = to_tf32(P.w[t1][(c1 * 32 + ci0) * 5 + tap] * sc1);
    v.z = to_tf32(P.w[t0][(c0 * 32 + ci1) * 5 + tap] * sc0);
    v.w = to_tf32(P.w[t1][(c1 * 32 + ci1) * 5 + tap] * sc1);
    g_wf[idx] = v;
}

// ---------------------------------------------------------------------------
// Conv via tf32 mma, x staged as B-fragment pairs (1 LDS.64 per frag).
// grid (4, 16, 16); 512 threads = 16 warps.
// smem: Xf2[4 o][136 col][4 q] float2 pairs (x[8o+q][col], x[8o+q+4][col])
//       | Wfs prepacked frags.
// ---------------------------------------------------------------------------
__global__ void __launch_bounds__(512, 1) conv_mma_kernel(ConvParams P) {
    extern __shared__ float sm[];
    float2* Xf2 = (float2*)sm;                 // 2176 f2 = 17408 B
    float4* Wfs = (float4*)(sm + 4352);        // 16*20*32 float4

    const int nc = blockIdx.x;
    const int h  = blockIdx.y;
    const int b  = blockIdx.z;
    const int tid = threadIdx.x;
    const int lane = tid & 31, wp = tid >> 5;
    const int g = lane >> 2, q = lane & 3;
    const int w0 = nc * 128;

    // Stage prepacked W fragments (coalesced)
#pragma unroll
    for (int i = 0; i < 20; i++)
        Wfs[i * 512 + tid] = g_wf[i * 512 + tid];

    // Stage x as fragment pairs: word (o,col,q') = (x[8o+q'][col], x[8o+q'+4][col])
    for (int w = tid; w < 2176; w += 512) {
        int p = w / 136, col = w - p * 136;
        int o = p >> 2, qr = p & 3;
        int wg = w0 - 2 + col;
        float v0 = 0.0f, v1 = 0.0f;
        if (wg >= 0 && wg < 512) {
            const float* xp = P.x + (size_t)((b * 32 + o * 8 + qr) * 16 + h) * 512 + wg;
            v0 = to_tf32(xp[0]);
            v1 = to_tf32(xp[4 * 16 * 512]);
        }
        Xf2[(o * 136 + col) * 4 + qr] = make_float2(v0, v1);
    }
    __syncthreads();

    float O[16][4];
#pragma unroll
    for (int j = 0; j < 16; j++)
#pragma unroll
        for (int u = 0; u < 4; u++) O[j][u] = 0.0f;

#pragma unroll 4
    for (int s = 0; s < 20; s++) {
        int tap = s >> 2, o = s & 3;
        float4 A = Wfs[(wp * 20 + s) * 32 + lane];
        unsigned a[4] = { __float_as_uint(A.x), __float_as_uint(A.y),
                          __float_as_uint(A.z), __float_as_uint(A.w) };
        const float2* bp = Xf2 + (o * 136 + g + tap) * 4 + q;
#pragma unroll
        for (int j = 0; j < 16; j++) {
            float2 bb = bp[j * 32];
            mma8(O[j], a, __float_as_uint(bb.x), __float_as_uint(bb.y));
        }
    }

    // Epilogue: + BN shift, LeakyReLU, store rows co0 and co0+8
    const int co0 = wp * 16 + g;
    const int t0 = co0 >> 6, c0 = co0 & 63;
    const int c1 = (co0 + 8) & 63;
    float sA = P.gamma[t0][c0] * rsqrtf(P.var[t0][c0] + BN_EPS);
    float shift0 = P.beta[t0][c0] - P.mean[t0][c0] * sA;
    float sB = P.gamma[t0][c1] * rsqrtf(P.var[t0][c1] + BN_EPS);
    float shift1 = P.beta[t0][c1] - P.mean[t0][c1] * sB;

    float* r0 = g_qkvp + (size_t)(((t0 * 16 + b) * 64 + c0) * 16 + h) * 512 + w0 + 2 * q;
    float* r1 = g_qkvp + (size_t)(((t0 * 16 + b) * 64 + c1) * 16 + h) * 512 + w0 + 2 * q;
#pragma unroll
    for (int j = 0; j < 16; j++) {
        float v0 = O[j][0] + shift0, v1 = O[j][1] + shift0;
        float v2 = O[j][2] + shift1, v3 = O[j][3] + shift1;
        v0 = (v0 >= 0.0f) ? v0 : LRELU_SLOPE * v0;
        v1 = (v1 >= 0.0f) ? v1 : LRELU_SLOPE * v1;
        v2 = (v2 >= 0.0f) ? v2 : LRELU_SLOPE * v2;
        v3 = (v3 >= 0.0f) ? v3 : LRELU_SLOPE * v3;
        *(float2*)(r0 + j * 8) = make_float2(v0, v1);
        *(float2*)(r1 + j * 8) = make_float2(v2, v3);
    }
}

// ---------------------------------------------------------------------------
// Attention per (b,c): Phase A tf32 mma (warp tile m64 x n32, B-frag reuse),
// 2-stage cross-warp softmax (max-free exp2), Phase B f16 mma m16n8k16 with
// k-permutation pi(2q)=q, pi(2q+1)=q+4 applied to BOTH V cols and P rows.
// 1024 CTAs, 512 threads, 152064 B smem.
// ---------------------------------------------------------------------------
__global__ void __launch_bounds__(512, 1) attn_kernel(float* __restrict__ out) {
    extern __shared__ float sm[];
    float2*   Qf2 = (float2*)sm;                  // 4096 f2 (tf32 frag pairs)
    float2*   Kf2 = Qf2 + 4096;                   // 4096 f2
    unsigned* Vh  = (unsigned*)(Kf2 + 4096);      // 4096 half2 words
    unsigned* Ph  = Vh + 4096;                    // 16384 half2 words
    float*    redP = (float*)(Ph + 16384);        // 64*17
    float*    redI = redP + 64 * 17;              // 64

    const int bc   = blockIdx.x;
    const int tid  = threadIdx.x;
    const int lane = tid & 31, wp = tid >> 5;
    const int g = lane >> 2, q = lane & 3;

    // ---- Staging ----
    {
        const float* qg = g_qkvp + (size_t)(0 * 1024 + bc) * 8192;
        const float* kg = g_qkvp + (size_t)(1 * 1024 + bc) * 8192;
        const int w = tid & 511;
#pragma unroll
        for (int j = 0; j < 8; j++) {
            int ks = j >> 2, qq = j & 3;
            int h0 = ks * 8 + qq;
            float a0 = qg[h0 * 512 + w] * LOG2E;
            float a1 = qg[(h0 + 4) * 512 + w] * LOG2E;
            Qf2[ks * 2048 + Fidx(w, qq)] = make_float2(to_tf32(a0), to_tf32(a1));
            float k0 = kg[h0 * 512 + w];
            float k1 = kg[(h0 + 4) * 512 + w];
            Kf2[ks * 2048 + Fidx(w, qq)] = make_float2(to_tf32(k0), to_tf32(k1));
        }
        // V as half2, pi-permuted pairs: word((kb*16+h)*8 + qs*2 + oh)
        //   = (V[h][16kb+8oh+qs], V[h][16kb+8oh+qs+4])
        const float* vg = g_qkvp + (size_t)(2 * 1024 + bc) * 8192;
#pragma unroll
        for (int it = 0; it < 8; it++) {
            int idx = tid + it * 512;
            int oh = idx & 1, qs = (idx >> 1) & 3, hh = (idx >> 3) & 15, kb = idx >> 7;
            int cc = kb * 16 + oh * 8 + qs;
            __half2 hv = __floats2half2_rn(vg[hh * 512 + cc], vg[hh * 512 + cc + 4]);
            Vh[idx] = *(unsigned*)&hv;
        }
    }
    __syncthreads();

    const int nbA   = wp * 32;                // Phase A n-stripe
    const int rbase = (g & 3) + 8 * (g >> 2); // row base within 16-row tile
    const int qs    = g & 3, hb = g >> 2;

    const int gbA = nbA + g;
    const float2* kE = Kf2 + gbA * 4 + (q ^ ((gbA >> 2) & 3));
    const float2* kO = Kf2 + (gbA + 8) * 4 + (q ^ (((gbA + 8) >> 2) & 3));

    float O[4][4];
#pragma unroll
    for (int t = 0; t < 4; t++)
#pragma unroll
        for (int u = 0; u < 4; u++) O[t][u] = 0.0f;

    for (int blk = 0; blk < 8; blk++) {
        // ---- Phase A: logits, warp tile = 64 rows x 32 cols ----
        float L[4][4][4];
#pragma unroll
        for (int mt = 0; mt < 4; mt++)
#pragma unroll
            for (int j = 0; j < 4; j++)
#pragma unroll
                for (int u = 0; u < 4; u++) L[mt][j][u] = 0.0f;

#pragma unroll
        for (int ks = 0; ks < 2; ks++) {
            float2 B0 = kE[ks * 2048];
            float2 B1 = kO[ks * 2048];
            float2 B2 = kE[ks * 2048 + 64];
            float2 B3 = kO[ks * 2048 + 64];
            unsigned b0x = __float_as_uint(B0.x), b0y = __float_as_uint(B0.y);
            unsigned b1x = __float_as_uint(B1.x), b1y = __float_as_uint(B1.y);
            unsigned b2x = __float_as_uint(B2.x), b2y = __float_as_uint(B2.y);
            unsigned b3x = __float_as_uint(B3.x), b3y = __float_as_uint(B3.y);
#pragma unroll
            for (int mt = 0; mt < 4; mt++) {
                int W1 = blk * 64 + mt * 16 + rbase;
                float2 p0 = Qf2[ks * 2048 + Fidx(W1, q)];
                float2 p1 = Qf2[ks * 2048 + Fidx(W1 + 4, q)];
                unsigned a[4] = { __float_as_uint(p0.x), __float_as_uint(p1.x),
                                  __float_as_uint(p0.y), __float_as_uint(p1.y) };
                mma8(L[mt][0], a, b0x, b0y);
                mma8(L[mt][1], a, b1x, b1y);
                mma8(L[mt][2], a, b2x, b2y);
                mma8(L[mt][3], a, b3x, b3y);
            }
        }

        // ---- exp2 + 2-stage row-sum reduction ----
        float sA[4], sB[4];
#pragma unroll
        for (int mt = 0; mt < 4; mt++) {
            float pa = 0.0f, pb = 0.0f;
#pragma unroll
            for (int j = 0; j < 4; j++) {
                float e0 = ex2(L[mt][j][0]); L[mt][j][0] = e0;
                float e1 = ex2(L[mt][j][1]); L[mt][j][1] = e1; pa += e0 + e1;
                float e2 = ex2(L[mt][j][2]); L[mt][j][2] = e2;
                float e3 = ex2(L[mt][j][3]); L[mt][j][3] = e3; pb += e2 + e3;
            }
            pa += __shfl_xor_sync(0xffffffffu, pa, 1);
            pa += __shfl_xor_sync(0xffffffffu, pa, 2);
            pb += __shfl_xor_sync(0xffffffffu, pb, 1);
            pb += __shfl_xor_sync(0xffffffffu, pb, 2);
            sA[mt] = pa; sB[mt] = pb;
        }
        if (q == 0) {
#pragma unroll
            for (int mt = 0; mt < 4; mt++) {
                redP[(mt * 16 + rbase) * 17 + wp]     = sA[mt];
                redP[(mt * 16 + rbase + 4) * 17 + wp] = sB[mt];
            }
        }
        __syncthreads();
        {
            int row = tid >> 3, jj = tid & 7;
            float s = redP[row * 17 + 2 * jj] + redP[row * 17 + 2 * jj + 1];
            s += __shfl_xor_sync(0xffffffffu, s, 1);
            s += __shfl_xor_sync(0xffffffffu, s, 2);
            s += __shfl_xor_sync(0xffffffffu, s, 4);
            if (jj == 0) redI[row] = __fdividef(1.0f, s);
        }
        __syncthreads();

        // ---- P store as half2 (rows r, r+4 packed; pi-layout) ----
#pragma unroll
        for (int mt = 0; mt < 4; mt++) {
            float invA = redI[mt * 16 + rbase];
            float invB = redI[mt * 16 + rbase + 4];
#pragma unroll
            for (int j = 0; j < 4; j++) {
#pragma unroll
                for (int c = 0; c < 2; c++) {
                    int col = nbA + j * 8 + 2 * q + c;
                    __half2 hp = __floats2half2_rn(L[mt][j][c] * invA,
                                                   L[mt][j][c + 2] * invB);
                    Ph[(mt * 512 + col) * 8 + ((qs * 2 + hb) ^ (col & 4))] =
                        *(unsigned*)&hp;
                }
            }
        }
        __syncthreads();

        // ---- Phase B: O += V @ P, f16 m16n8k16 ----
#pragma unroll
        for (int ks = 0; ks < 4; ks++) {
            int kbV = blk * 4 + ks;
            uint2 va = *(const uint2*)(Vh + ((kbV * 16 + g) * 4 + q) * 2);
            uint2 vb = *(const uint2*)(Vh + ((kbV * 16 + g + 8) * 4 + q) * 2);
            unsigned a[4] = { va.x, vb.x, va.y, vb.y };
#pragma unroll
            for (int nt = 0; nt < 4; nt++) {
                int col = wp * 32 + nt * 8 + g;
                uint2 bb = *(const uint2*)(Ph + (ks * 512 + col) * 8 + ((q * 2) ^ (col & 4)));
                mma16h(O[nt], a, bb.x, bb.y);
            }
        }
        __syncthreads();
    }

    // ---- epilogue: + PE, store ----
    const float* pe = g_qkvp + (size_t)(3 * 1024 + bc) * 8192;
    float* dst = out + (size_t)bc * 8192;
#pragma unroll
    for (int t = 0; t < 4; t++) {
        int col = wp * 32 + t * 8 + 2 * q;
        float2 pA = *(const float2*)(pe + g * 512 + col);
        float2 pB = *(const float2*)(pe + (g + 8) * 512 + col);
        *(float2*)(dst + g * 512 + col) =
            make_float2(O[t][0] + pA.x, O[t][1] + pA.y);
        *(float2*)(dst + (g + 8) * 512 + col) =
            make_float2(O[t][2] + pB.x, O[t][3] + pB.y);
    }
}

// ---------------------------------------------------------------------------
extern "C" void kernel_launch(void* const* d_in, const int* in_sizes, int n_in,
                              void* d_out, int out_size) {
    (void)in_sizes; (void)n_in; (void)out_size;

    ConvParams P;
    P.x = (const float*)d_in[0];
    for (int i = 0; i < 4; i++) {
        P.w[i]     = (const float*)d_in[1 + i * 5 + 0];
        P.gamma[i] = (const float*)d_in[1 + i * 5 + 1];
        P.beta[i]  = (const float*)d_in[1 + i * 5 + 2];
        P.mean[i]  = (const float*)d_in[1 + i * 5 + 3];
        P.var[i]   = (const float*)d_in[1 + i * 5 + 4];
    }

    const int CONV_SMEM = 2176 * 8 + 16 * 20 * 32 * 16;        // 181248 B
    const int ATTN_SMEM = 4096 * 8 * 2 + 4096 * 4 + 16384 * 4
                        + (64 * 17) * 4 + 64 * 4;              // 152064 B
    cudaFuncSetAttribute(conv_mma_kernel, cudaFuncAttributeMaxDynamicSharedMemorySize, CONV_SMEM);
    cudaFuncSetAttribute(attn_kernel, cudaFuncAttributeMaxDynamicSharedMemorySize, ATTN_SMEM);

    prepack_kernel<<<40, 256>>>(P);
    conv_mma_kernel<<<dim3(4, 16, 16), 512, CONV_SMEM>>>(P);
    attn_kernel<<<1024, 512, ATTN_SMEM>>>((float*)d_out);
}